// round 12
// baseline (speedup 1.0000x reference)
#include <cuda_runtime.h>
#include <cuda_bf16.h>
#include <cuda_fp16.h>
#include <cstdint>

#define NN 100000
#define EE 1600000
#define D 128
#define NTILES ((NN + 127) / 128)   // 782

#define SCAN_CHUNK 1024
#define SCAN_NBLK ((NN + SCAN_CHUNK - 1) / SCAN_CHUNK)   // 98

// Padded smem strides (bf16 elements): 272B rows -> conflict-free ldmatrix
#define SA 136
#define A_BYTES (128 * SA * 2)          // 34816
#define GEMM_DSMEM (4 * A_BYTES)        // A_hi, A_lo, B_hi, B_lo = 139264

// ---------------------------------------------------------------------------
// Scratch (static __device__ arrays — allocation is forbidden)
// ---------------------------------------------------------------------------
__device__ int g_is64;
__device__ __align__(16) int    g_cnt[NN];
__device__ __align__(16) int    g_rowptr[NN + 1];
__device__ __align__(16) int    g_cursor[NN];
__device__ __align__(16) int    g_col[EE];        // src ids grouped by dst
__device__ __align__(16) int    g_part[SCAN_NBLK];
__device__ __align__(16) float  g_dinv[NN];
__device__ __align__(16) __half g_h16[(size_t)NN * D];    // layer-1 h (fp16)
__device__ __align__(16) __half g_h16b[(size_t)NN * D];   // layer-2 h (fp16)
__device__ __align__(16) __nv_bfloat16 g_x2h[(size_t)NN * D];  // x2 hi (bf16)
__device__ __align__(16) __nv_bfloat16 g_x2l[(size_t)NN * D];  // x2 lo (bf16)
__device__ __align__(16) __nv_bfloat16 g_wh1[16384], g_wl1[16384];
__device__ __align__(16) __nv_bfloat16 g_wh2[16384], g_wl2[16384];

// ---------------------------------------------------------------------------
// PTX helpers
// ---------------------------------------------------------------------------
__device__ __forceinline__ uint32_t smem_u32(const void* p) {
    uint32_t a;
    asm("{ .reg .u64 t; cvta.to.shared.u64 t, %1; cvt.u32.u64 %0, t; }"
        : "=r"(a) : "l"(p));
    return a;
}
__device__ __forceinline__ void ldmatrix_x4(uint32_t* r, uint32_t addr) {
    asm volatile("ldmatrix.sync.aligned.m8n8.x4.shared.b16 {%0,%1,%2,%3}, [%4];"
                 : "=r"(r[0]), "=r"(r[1]), "=r"(r[2]), "=r"(r[3]) : "r"(addr));
}
__device__ __forceinline__ void ldmatrix_x4_t(uint32_t* r, uint32_t addr) {
    asm volatile("ldmatrix.sync.aligned.m8n8.x4.trans.shared.b16 {%0,%1,%2,%3}, [%4];"
                 : "=r"(r[0]), "=r"(r[1]), "=r"(r[2]), "=r"(r[3]) : "r"(addr));
}
__device__ __forceinline__ void mma_bf16(float* c, const uint32_t* a,
                                         const uint32_t* b) {
    asm volatile(
        "mma.sync.aligned.m16n8k16.row.col.f32.bf16.bf16.f32 "
        "{%0,%1,%2,%3}, {%4,%5,%6,%7}, {%8,%9}, {%0,%1,%2,%3};"
        : "+f"(c[0]), "+f"(c[1]), "+f"(c[2]), "+f"(c[3])
        : "r"(a[0]), "r"(a[1]), "r"(a[2]), "r"(a[3]), "r"(b[0]), "r"(b[1]));
}

// bf16 hi/lo split of a float4, packed into two uint2
__device__ __forceinline__ void split_bf16(const float4& x, uint2& ph, uint2& pl) {
    __nv_bfloat16 h0 = __float2bfloat16(x.x);
    __nv_bfloat16 h1 = __float2bfloat16(x.y);
    __nv_bfloat16 h2 = __float2bfloat16(x.z);
    __nv_bfloat16 h3 = __float2bfloat16(x.w);
    ph.x = ((uint32_t)__bfloat16_as_ushort(h1) << 16) | __bfloat16_as_ushort(h0);
    ph.y = ((uint32_t)__bfloat16_as_ushort(h3) << 16) | __bfloat16_as_ushort(h2);
    __nv_bfloat16 l0 = __float2bfloat16(x.x - __bfloat162float(h0));
    __nv_bfloat16 l1 = __float2bfloat16(x.y - __bfloat162float(h1));
    __nv_bfloat16 l2 = __float2bfloat16(x.z - __bfloat162float(h2));
    __nv_bfloat16 l3 = __float2bfloat16(x.w - __bfloat162float(h3));
    pl.x = ((uint32_t)__bfloat16_as_ushort(l1) << 16) | __bfloat16_as_ushort(l0);
    pl.y = ((uint32_t)__bfloat16_as_ushort(l3) << 16) | __bfloat16_as_ushort(l2);
}

// ---------------------------------------------------------------------------
// Graph preprocessing
// ---------------------------------------------------------------------------
__global__ void detect_zero_kernel(const int* __restrict__ ei32) {
    int i = blockIdx.x * blockDim.x + threadIdx.x;
    if (i < NN) g_cnt[i] = 0;
    if (i == 0) {
        int ored = 0;
        #pragma unroll
        for (int k = 0; k < 32; k++) ored |= ei32[2 * k + 1];
        g_is64 = (ored == 0) ? 1 : 0;
    }
}

__global__ void hist_kernel(const int* __restrict__ ei32) {
    int e = blockIdx.x * blockDim.x + threadIdx.x;
    if (e >= EE) return;
    int is64 = g_is64;
    int d = is64 ? ei32[2 * ((long long)EE + e)] : ei32[EE + e];
    d = min(max(d, 0), NN - 1);
    atomicAdd(&g_cnt[d], 1);
}

// dinv only needs cnt (deg = cnt + 1): runs on the side branch
__global__ void dinv_kernel() {
    int i = blockIdx.x * blockDim.x + threadIdx.x;
    if (i < NN) g_dinv[i] = rsqrtf((float)(g_cnt[i] + 1));
}

__global__ void scan1_kernel() {
    __shared__ int sh[SCAN_CHUNK];
    int i = blockIdx.x * SCAN_CHUNK + threadIdx.x;
    int v = (i < NN) ? g_cnt[i] : 0;
    sh[threadIdx.x] = v;
    __syncthreads();
    #pragma unroll
    for (int off = 1; off < SCAN_CHUNK; off <<= 1) {
        int t = (threadIdx.x >= off) ? sh[threadIdx.x - off] : 0;
        __syncthreads();
        sh[threadIdx.x] += t;
        __syncthreads();
    }
    if (i <= NN - 1) g_rowptr[i] = sh[threadIdx.x] - v;
    if (threadIdx.x == SCAN_CHUNK - 1) g_part[blockIdx.x] = sh[threadIdx.x];
}

__global__ void scan2_kernel() {
    __shared__ int sh[128];
    int t = threadIdx.x;
    int v = (t < SCAN_NBLK) ? g_part[t] : 0;
    sh[t] = v;
    __syncthreads();
    #pragma unroll
    for (int off = 1; off < 128; off <<= 1) {
        int u = (t >= off) ? sh[t - off] : 0;
        __syncthreads();
        sh[t] += u;
        __syncthreads();
    }
    if (t < SCAN_NBLK) g_part[t] = sh[t] - v;
    if (t == 127) g_rowptr[NN] = sh[127];
}

__global__ void scan3_kernel() {   // offsets + cursors
    int i = blockIdx.x * blockDim.x + threadIdx.x;
    if (i >= NN) return;
    int rp = g_rowptr[i] + g_part[i / SCAN_CHUNK];
    g_rowptr[i] = rp;
    g_cursor[i] = rp;
}

__global__ void fill_kernel(const int* __restrict__ ei32) {
    int e = blockIdx.x * blockDim.x + threadIdx.x;
    if (e >= EE) return;
    int is64 = g_is64;
    int s = is64 ? ei32[2 * (long long)e] : ei32[e];
    int d = is64 ? ei32[2 * ((long long)EE + e)] : ei32[EE + e];
    s = min(max(s, 0), NN - 1);
    d = min(max(d, 0), NN - 1);
    int pos = atomicAdd(&g_cursor[d], 1);
    g_col[pos] = s;
}

// Prep both W: split fp32 into bf16 hi/lo, row-major [k][n]
__global__ void prepw_kernel(const float* __restrict__ W1,
                             const float* __restrict__ W2) {
    int e = blockIdx.x * blockDim.x + threadIdx.x;
    if (e >= 16384) return;
    float v1 = W1[e];
    __nv_bfloat16 h1 = __float2bfloat16(v1);
    g_wh1[e] = h1;
    g_wl1[e] = __float2bfloat16(v1 - __bfloat162float(h1));
    float v2 = W2[e];
    __nv_bfloat16 h2 = __float2bfloat16(v2);
    g_wh2[e] = h2;
    g_wl2[e] = __float2bfloat16(v2 - __bfloat162float(h2));
}

// ---------------------------------------------------------------------------
// Shared GEMM pieces (512 threads, 16 warps 4x4, 128x128 tile)
// ---------------------------------------------------------------------------
__device__ __forceinline__ void stage_B(__nv_bfloat16* sBh, __nv_bfloat16* sBl,
                                        const __nv_bfloat16* wh,
                                        const __nv_bfloat16* wl, int tid) {
    #pragma unroll
    for (int it = 0; it < 4; it++) {
        int idx = it * 512 + tid;         // 2048 uint4 per array
        int k = idx >> 4;
        int part = idx & 15;
        uint4 vh = ((const uint4*)wh)[idx];
        uint4 vl = ((const uint4*)wl)[idx];
        int off = k * SA + part * 8;
        *(uint4*)(sBh + off) = vh;
        *(uint4*)(sBl + off) = vl;
    }
}

// Full MMA + fp16 epilogue: hout[m,:] = fp16(dinv[m] * A@B)
__device__ __forceinline__ void mma_tile(uint32_t baseAh, uint32_t baseAl,
                                         uint32_t baseBh, uint32_t baseBl,
                                         int wid, int lane, int row0,
                                         __half* hout) {
    int warp_m = wid & 3;
    int warp_n = wid >> 2;

    float acc[2][4][4];
    #pragma unroll
    for (int i = 0; i < 2; i++)
        #pragma unroll
        for (int j = 0; j < 4; j++)
            #pragma unroll
            for (int q = 0; q < 4; q++) acc[i][j][q] = 0.0f;

    int a_row = warp_m * 32 + (lane & 15);
    int a_kadd = (lane >> 4) * 8;
    int b_krow = (lane & 7) + ((lane >> 3) & 1) * 8;
    int b_ncol0 = warp_n * 32 + (lane >> 4) * 8;

    #pragma unroll
    for (int ks = 0; ks < 8; ks++) {
        int k0 = ks * 16;
        uint32_t ah[2][4], al[2][4];
        #pragma unroll
        for (int mt = 0; mt < 2; mt++) {
            uint32_t off = (uint32_t)((a_row + mt * 16) * SA + k0 + a_kadd) * 2;
            ldmatrix_x4(ah[mt], baseAh + off);
            ldmatrix_x4(al[mt], baseAl + off);
        }
        uint32_t bh[4][2], bl[4][2];
        #pragma unroll
        for (int np = 0; np < 2; np++) {
            uint32_t off = (uint32_t)((k0 + b_krow) * SA + b_ncol0 + np * 16) * 2;
            uint32_t t4[4];
            ldmatrix_x4_t(t4, baseBh + off);
            bh[np * 2 + 0][0] = t4[0]; bh[np * 2 + 0][1] = t4[1];
            bh[np * 2 + 1][0] = t4[2]; bh[np * 2 + 1][1] = t4[3];
            ldmatrix_x4_t(t4, baseBl + off);
            bl[np * 2 + 0][0] = t4[0]; bl[np * 2 + 0][1] = t4[1];
            bl[np * 2 + 1][0] = t4[2]; bl[np * 2 + 1][1] = t4[3];
        }
        #pragma unroll
        for (int mt = 0; mt < 2; mt++)
            #pragma unroll
            for (int nt = 0; nt < 4; nt++) {
                mma_bf16(acc[mt][nt], ah[mt], bh[nt]);
                mma_bf16(acc[mt][nt], al[mt], bh[nt]);
                mma_bf16(acc[mt][nt], ah[mt], bl[nt]);
            }
    }

    #pragma unroll
    for (int mt = 0; mt < 2; mt++) {
        int r_lo = row0 + warp_m * 32 + mt * 16 + (lane >> 2);
        int r_hi = r_lo + 8;
        float dv_lo = (r_lo < NN) ? g_dinv[r_lo] : 0.0f;
        float dv_hi = (r_hi < NN) ? g_dinv[r_hi] : 0.0f;
        #pragma unroll
        for (int nt = 0; nt < 4; nt++) {
            int col = warp_n * 32 + nt * 8 + (lane & 3) * 2;
            if (r_lo < NN)
                *(__half2*)(hout + (size_t)r_lo * D + col) =
                    __floats2half2_rn(acc[mt][nt][0] * dv_lo,
                                      acc[mt][nt][1] * dv_lo);
            if (r_hi < NN)
                *(__half2*)(hout + (size_t)r_hi * D + col) =
                    __floats2half2_rn(acc[mt][nt][2] * dv_hi,
                                      acc[mt][nt][3] * dv_hi);
        }
    }
}

// fp16 row accumulate (half-warp layout): acc[0..7] += hbuf[s][hl*8 .. hl*8+7]
__device__ __forceinline__ void add_row16q(float* acc, const __half* hbuf,
                                           int s, int hl) {
    uint4 raw = *(const uint4*)(hbuf + (size_t)s * D + hl * 8);
    float2 f0 = __half22float2(*reinterpret_cast<const __half2*>(&raw.x));
    float2 f1 = __half22float2(*reinterpret_cast<const __half2*>(&raw.y));
    float2 f2 = __half22float2(*reinterpret_cast<const __half2*>(&raw.z));
    float2 f3 = __half22float2(*reinterpret_cast<const __half2*>(&raw.w));
    acc[0] += f0.x; acc[1] += f0.y; acc[2] += f1.x; acc[3] += f1.y;
    acc[4] += f2.x; acc[5] += f2.y; acc[6] += f3.x; acc[7] += f3.y;
}

// Half-warp-per-node CSR gather: 16 lanes per node, uint4 row loads.
// acc[0..7] = self + sum of neighbor rows (cols hl*8 .. hl*8+7).
__device__ __forceinline__ void gather_core_hw(float* acc, const __half* hbuf,
                                               int node, int half, int hl) {
    int beg = g_rowptr[node];
    int end = g_rowptr[node + 1];
    #pragma unroll
    for (int i = 0; i < 8; i++) acc[i] = 0.0f;
    add_row16q(acc, hbuf, node, hl);   // self loop
    int sbase = half << 4;
    for (int j = beg; j < end; j += 16) {
        int e = j + hl;
        int c = (e < end) ? __ldg(&g_col[e]) : 0;
        int m = min(16, end - j);
        int t = 0;
        for (; t + 4 <= m; t += 4) {
            int s0 = __shfl_sync(0xffffffffu, c, sbase + t + 0);
            int s1 = __shfl_sync(0xffffffffu, c, sbase + t + 1);
            int s2 = __shfl_sync(0xffffffffu, c, sbase + t + 2);
            int s3 = __shfl_sync(0xffffffffu, c, sbase + t + 3);
            add_row16q(acc, hbuf, s0, hl);
            add_row16q(acc, hbuf, s1, hl);
            add_row16q(acc, hbuf, s2, hl);
            add_row16q(acc, hbuf, s3, hl);
        }
        for (; t < m; t++) {
            int s = __shfl_sync(0xffffffffu, c, sbase + t);
            add_row16q(acc, hbuf, s, hl);
        }
    }
}

// ---------------------------------------------------------------------------
// GEMM layer 1: A staged from fp32 X, B = W1 -> g_h16 = fp16(dinv * X@W1)
// ---------------------------------------------------------------------------
__global__ void __launch_bounds__(512)
gemm1_kernel(const float* __restrict__ X) {
    extern __shared__ char dsm[];
    __nv_bfloat16* sAh = (__nv_bfloat16*)dsm;
    __nv_bfloat16* sAl = (__nv_bfloat16*)(dsm + A_BYTES);
    __nv_bfloat16* sBh = (__nv_bfloat16*)(dsm + 2 * A_BYTES);
    __nv_bfloat16* sBl = (__nv_bfloat16*)(dsm + 3 * A_BYTES);

    int tid = threadIdx.x;
    int wid = tid >> 5;
    int lane = tid & 31;
    int row0 = blockIdx.x * 128;

    #pragma unroll
    for (int it = 0; it < 8; it++) {
        int f = it * 512 + tid;
        int r = f >> 5;
        int p4 = f & 31;
        int gr = row0 + r;
        float4 v = make_float4(0.f, 0.f, 0.f, 0.f);
        if (gr < NN) v = *(const float4*)(X + (size_t)gr * D + p4 * 4);
        uint2 ph, pl;
        split_bf16(v, ph, pl);
        int off = r * SA + p4 * 4;
        *(uint2*)(sAh + off) = ph;
        *(uint2*)(sAl + off) = pl;
    }
    stage_B(sBh, sBl, g_wh1, g_wl1, tid);
    __syncthreads();

    uint32_t baseAh = smem_u32(sAh);
    mma_tile(baseAh, baseAh + A_BYTES, baseAh + 2 * A_BYTES,
             baseAh + 3 * A_BYTES, wid, lane, row0, g_h16);
}

// ---------------------------------------------------------------------------
// Gather layer 1 (half-warp/node): x2 = relu(dinv*(self+nbrs) + b1) bf16 hi/lo
// ---------------------------------------------------------------------------
__global__ void __launch_bounds__(256)
gather1_kernel(const float* __restrict__ b1) {
    int gthread = blockIdx.x * blockDim.x + threadIdx.x;
    int node = gthread >> 4;
    if (node >= NN) return;
    int lane = threadIdx.x & 31;
    int half = lane >> 4;
    int hl = lane & 15;

    float acc[8];
    gather_core_hw(acc, g_h16, node, half, hl);

    float dv = g_dinv[node];
    float4 b_lo = *(const float4*)(b1 + hl * 8);
    float4 b_hi = *(const float4*)(b1 + hl * 8 + 4);
    float4 xa, xb;
    xa.x = fmaxf(acc[0] * dv + b_lo.x, 0.f);
    xa.y = fmaxf(acc[1] * dv + b_lo.y, 0.f);
    xa.z = fmaxf(acc[2] * dv + b_lo.z, 0.f);
    xa.w = fmaxf(acc[3] * dv + b_lo.w, 0.f);
    xb.x = fmaxf(acc[4] * dv + b_hi.x, 0.f);
    xb.y = fmaxf(acc[5] * dv + b_hi.y, 0.f);
    xb.z = fmaxf(acc[6] * dv + b_hi.z, 0.f);
    xb.w = fmaxf(acc[7] * dv + b_hi.w, 0.f);

    uint2 pha, pla, phb, plb;
    split_bf16(xa, pha, pla);
    split_bf16(xb, phb, plb);
    uint4 vh = make_uint4(pha.x, pha.y, phb.x, phb.y);
    uint4 vl = make_uint4(pla.x, pla.y, plb.x, plb.y);
    *(uint4*)(g_x2h + (size_t)node * D + hl * 8) = vh;
    *(uint4*)(g_x2l + (size_t)node * D + hl * 8) = vl;
}

// ---------------------------------------------------------------------------
// GEMM layer 2: A staged from prepped bf16 hi/lo x2 -> g_h16b
// ---------------------------------------------------------------------------
__global__ void __launch_bounds__(512)
gemm2_kernel() {
    extern __shared__ char dsm[];
    __nv_bfloat16* sAh = (__nv_bfloat16*)dsm;
    __nv_bfloat16* sAl = (__nv_bfloat16*)(dsm + A_BYTES);
    __nv_bfloat16* sBh = (__nv_bfloat16*)(dsm + 2 * A_BYTES);
    __nv_bfloat16* sBl = (__nv_bfloat16*)(dsm + 3 * A_BYTES);

    int tid = threadIdx.x;
    int wid = tid >> 5;
    int lane = tid & 31;
    int row0 = blockIdx.x * 128;

    #pragma unroll
    for (int it = 0; it < 8; it++) {
        int f = it * 512 + tid;           // 4096 uint2 slots
        int r = f >> 5;
        int p4 = f & 31;
        int gr = row0 + r;
        uint2 vh = make_uint2(0u, 0u), vl = make_uint2(0u, 0u);
        if (gr < NN) {
            vh = *(const uint2*)(g_x2h + (size_t)gr * D + p4 * 4);
            vl = *(const uint2*)(g_x2l + (size_t)gr * D + p4 * 4);
        }
        int off = r * SA + p4 * 4;
        *(uint2*)(sAh + off) = vh;
        *(uint2*)(sAl + off) = vl;
    }
    stage_B(sBh, sBl, g_wh2, g_wl2, tid);
    __syncthreads();

    uint32_t baseAh = smem_u32(sAh);
    mma_tile(baseAh, baseAh + A_BYTES, baseAh + 2 * A_BYTES,
             baseAh + 3 * A_BYTES, wid, lane, row0, g_h16b);
}

// ---------------------------------------------------------------------------
// Final gather (half-warp/node): out = (self+nbrs)*dinv + b2, fp32
// ---------------------------------------------------------------------------
__global__ void __launch_bounds__(256)
gather2_kernel(const float* __restrict__ b2, float* __restrict__ out) {
    int gthread = blockIdx.x * blockDim.x + threadIdx.x;
    int node = gthread >> 4;
    if (node >= NN) return;
    int lane = threadIdx.x & 31;
    int half = lane >> 4;
    int hl = lane & 15;

    float acc[8];
    gather_core_hw(acc, g_h16b, node, half, hl);

    float sc = g_dinv[node];
    float4 b_lo = *(const float4*)(b2 + hl * 8);
    float4 b_hi = *(const float4*)(b2 + hl * 8 + 4);
    float4 ra, rb;
    ra.x = acc[0] * sc + b_lo.x;
    ra.y = acc[1] * sc + b_lo.y;
    ra.z = acc[2] * sc + b_lo.z;
    ra.w = acc[3] * sc + b_lo.w;
    rb.x = acc[4] * sc + b_hi.x;
    rb.y = acc[5] * sc + b_hi.y;
    rb.z = acc[6] * sc + b_hi.z;
    rb.w = acc[7] * sc + b_hi.w;
    *(float4*)(out + (size_t)node * D + hl * 8) = ra;
    *(float4*)(out + (size_t)node * D + hl * 8 + 4) = rb;
}

// ---------------------------------------------------------------------------
// Launch — kernel launches + captured event fork/join (graph-capture safe;
// stream/events created on the FIRST call, which the harness runs uncaptured)
// ---------------------------------------------------------------------------
extern "C" void kernel_launch(void* const* d_in, const int* in_sizes, int n_in,
                              void* d_out, int out_size) {
    const float* x  = (const float*)d_in[0];
    const int*   ei = (const int*)d_in[1];
    const float* W1 = (const float*)d_in[2];
    const float* b1 = (const float*)d_in[3];
    const float* W2 = (const float*)d_in[4];
    const float* b2 = (const float*)d_in[5];
    float* out = (float*)d_out;

    static cudaStream_t s2 = nullptr;
    static cudaEvent_t evFork = nullptr, evJoin = nullptr;
    if (!s2) {
        cudaFuncSetAttribute(gemm1_kernel,
                             cudaFuncAttributeMaxDynamicSharedMemorySize,
                             GEMM_DSMEM);
        cudaFuncSetAttribute(gemm2_kernel,
                             cudaFuncAttributeMaxDynamicSharedMemorySize,
                             GEMM_DSMEM);
        cudaStreamCreateWithFlags(&s2, cudaStreamNonBlocking);
        cudaEventCreateWithFlags(&evFork, cudaEventDisableTiming);
        cudaEventCreateWithFlags(&evJoin, cudaEventDisableTiming);
    }

    const int T = 256;
    const int nb_n    = (NN + T - 1) / T;
    const int nb_e    = (EE + T - 1) / T;
    const int nb_gath = (NN * 16 + T - 1) / T;   // half-warp per node

    // Main stream: degree histogram
    detect_zero_kernel<<<nb_n, T>>>(ei);
    hist_kernel<<<nb_e, T>>>(ei);

    // Fork: side branch computes prepw + dinv + gemm1 (needs only cnt),
    // while main does scan + fill (CSR build). Disjoint write sets.
    cudaEventRecord(evFork, 0);
    cudaStreamWaitEvent(s2, evFork, 0);

    prepw_kernel<<<64, 256, 0, s2>>>(W1, W2);
    dinv_kernel<<<nb_n, T, 0, s2>>>();
    gemm1_kernel<<<NTILES, 512, GEMM_DSMEM, s2>>>(x);
    cudaEventRecord(evJoin, s2);

    // Main: CSR build
    scan1_kernel<<<SCAN_NBLK, SCAN_CHUNK>>>();
    scan2_kernel<<<1, 128>>>();
    scan3_kernel<<<nb_n, T>>>();
    fill_kernel<<<nb_e, T>>>(ei);

    // Join: gather1 needs CSR + g_h16 + dinv
    cudaStreamWaitEvent(0, evJoin, 0);

    gather1_kernel<<<nb_gath, T>>>(b1);
    gemm2_kernel<<<NTILES, 512, GEMM_DSMEM>>>();
    gather2_kernel<<<nb_gath, T>>>(b2, out);
}

// round 13
// speedup vs baseline: 1.0092x; 1.0092x over previous
#include <cuda_runtime.h>
#include <cuda_bf16.h>
#include <cuda_fp16.h>
#include <cstdint>

#define NN 100000
#define EE 1600000
#define D 128
#define NTILES ((NN + 127) / 128)   // 782
#define NSLICE 4
#define SLICE_N ((NN + NSLICE - 1) / NSLICE)          // 25000
#define SLICE_TILES ((SLICE_N + 127) / 128)           // 196

#define SCAN_CHUNK 1024
#define SCAN_NBLK ((NN + SCAN_CHUNK - 1) / SCAN_CHUNK)   // 98

// Padded smem strides (bf16 elements): 272B rows -> conflict-free ldmatrix
#define SA 136
#define A_BYTES (128 * SA * 2)          // 34816
#define GEMM_DSMEM (4 * A_BYTES)        // A_hi, A_lo, B_hi, B_lo = 139264

// ---------------------------------------------------------------------------
// Scratch (static __device__ arrays — allocation is forbidden)
// ---------------------------------------------------------------------------
__device__ int g_is64;
__device__ __align__(16) int    g_cnt[NN];
__device__ __align__(16) int    g_rowptr[NN + 1];
__device__ __align__(16) int    g_cursor[NN];
__device__ __align__(16) int    g_col[EE];        // src ids grouped by dst
__device__ __align__(16) int    g_part[SCAN_NBLK];
__device__ __align__(16) float  g_dinv[NN];
__device__ __align__(16) __half g_h16[(size_t)NN * D];    // layer-1 h (fp16)
__device__ __align__(16) __half g_h16b[(size_t)NN * D];   // layer-2 h (fp16)
__device__ __align__(16) __nv_bfloat16 g_x2h[(size_t)NN * D];  // x2 hi (bf16)
__device__ __align__(16) __nv_bfloat16 g_x2l[(size_t)NN * D];  // x2 lo (bf16)
__device__ __align__(16) __nv_bfloat16 g_wh1[16384], g_wl1[16384];
__device__ __align__(16) __nv_bfloat16 g_wh2[16384], g_wl2[16384];

// ---------------------------------------------------------------------------
// PTX helpers
// ---------------------------------------------------------------------------
__device__ __forceinline__ uint32_t smem_u32(const void* p) {
    uint32_t a;
    asm("{ .reg .u64 t; cvta.to.shared.u64 t, %1; cvt.u32.u64 %0, t; }"
        : "=r"(a) : "l"(p));
    return a;
}
__device__ __forceinline__ void ldmatrix_x4(uint32_t* r, uint32_t addr) {
    asm volatile("ldmatrix.sync.aligned.m8n8.x4.shared.b16 {%0,%1,%2,%3}, [%4];"
                 : "=r"(r[0]), "=r"(r[1]), "=r"(r[2]), "=r"(r[3]) : "r"(addr));
}
__device__ __forceinline__ void ldmatrix_x4_t(uint32_t* r, uint32_t addr) {
    asm volatile("ldmatrix.sync.aligned.m8n8.x4.trans.shared.b16 {%0,%1,%2,%3}, [%4];"
                 : "=r"(r[0]), "=r"(r[1]), "=r"(r[2]), "=r"(r[3]) : "r"(addr));
}
__device__ __forceinline__ void mma_bf16(float* c, const uint32_t* a,
                                         const uint32_t* b) {
    asm volatile(
        "mma.sync.aligned.m16n8k16.row.col.f32.bf16.bf16.f32 "
        "{%0,%1,%2,%3}, {%4,%5,%6,%7}, {%8,%9}, {%0,%1,%2,%3};"
        : "+f"(c[0]), "+f"(c[1]), "+f"(c[2]), "+f"(c[3])
        : "r"(a[0]), "r"(a[1]), "r"(a[2]), "r"(a[3]), "r"(b[0]), "r"(b[1]));
}

// bf16 hi/lo split of a float4, packed into two uint2
__device__ __forceinline__ void split_bf16(const float4& x, uint2& ph, uint2& pl) {
    __nv_bfloat16 h0 = __float2bfloat16(x.x);
    __nv_bfloat16 h1 = __float2bfloat16(x.y);
    __nv_bfloat16 h2 = __float2bfloat16(x.z);
    __nv_bfloat16 h3 = __float2bfloat16(x.w);
    ph.x = ((uint32_t)__bfloat16_as_ushort(h1) << 16) | __bfloat16_as_ushort(h0);
    ph.y = ((uint32_t)__bfloat16_as_ushort(h3) << 16) | __bfloat16_as_ushort(h2);
    __nv_bfloat16 l0 = __float2bfloat16(x.x - __bfloat162float(h0));
    __nv_bfloat16 l1 = __float2bfloat16(x.y - __bfloat162float(h1));
    __nv_bfloat16 l2 = __float2bfloat16(x.z - __bfloat162float(h2));
    __nv_bfloat16 l3 = __float2bfloat16(x.w - __bfloat162float(h3));
    pl.x = ((uint32_t)__bfloat16_as_ushort(l1) << 16) | __bfloat16_as_ushort(l0);
    pl.y = ((uint32_t)__bfloat16_as_ushort(l3) << 16) | __bfloat16_as_ushort(l2);
}

// ---------------------------------------------------------------------------
// Graph preprocessing
// ---------------------------------------------------------------------------
__global__ void detect_zero_kernel(const int* __restrict__ ei32) {
    int i = blockIdx.x * blockDim.x + threadIdx.x;
    if (i < NN) g_cnt[i] = 0;
    if (i == 0) {
        int ored = 0;
        #pragma unroll
        for (int k = 0; k < 32; k++) ored |= ei32[2 * k + 1];
        g_is64 = (ored == 0) ? 1 : 0;
    }
}

__global__ void hist_kernel(const int* __restrict__ ei32) {
    int e = blockIdx.x * blockDim.x + threadIdx.x;
    if (e >= EE) return;
    int is64 = g_is64;
    int d = is64 ? ei32[2 * ((long long)EE + e)] : ei32[EE + e];
    d = min(max(d, 0), NN - 1);
    atomicAdd(&g_cnt[d], 1);
}

// dinv only needs cnt (deg = cnt + 1): runs on the side branch
__global__ void dinv_kernel() {
    int i = blockIdx.x * blockDim.x + threadIdx.x;
    if (i < NN) g_dinv[i] = rsqrtf((float)(g_cnt[i] + 1));
}

__global__ void scan1_kernel() {
    __shared__ int sh[SCAN_CHUNK];
    int i = blockIdx.x * SCAN_CHUNK + threadIdx.x;
    int v = (i < NN) ? g_cnt[i] : 0;
    sh[threadIdx.x] = v;
    __syncthreads();
    #pragma unroll
    for (int off = 1; off < SCAN_CHUNK; off <<= 1) {
        int t = (threadIdx.x >= off) ? sh[threadIdx.x - off] : 0;
        __syncthreads();
        sh[threadIdx.x] += t;
        __syncthreads();
    }
    if (i <= NN - 1) g_rowptr[i] = sh[threadIdx.x] - v;
    if (threadIdx.x == SCAN_CHUNK - 1) g_part[blockIdx.x] = sh[threadIdx.x];
}

__global__ void scan2_kernel() {
    __shared__ int sh[128];
    int t = threadIdx.x;
    int v = (t < SCAN_NBLK) ? g_part[t] : 0;
    sh[t] = v;
    __syncthreads();
    #pragma unroll
    for (int off = 1; off < 128; off <<= 1) {
        int u = (t >= off) ? sh[t - off] : 0;
        __syncthreads();
        sh[t] += u;
        __syncthreads();
    }
    if (t < SCAN_NBLK) g_part[t] = sh[t] - v;
    if (t == 127) g_rowptr[NN] = sh[127];
}

__global__ void scan3_kernel() {   // offsets + cursors
    int i = blockIdx.x * blockDim.x + threadIdx.x;
    if (i >= NN) return;
    int rp = g_rowptr[i] + g_part[i / SCAN_CHUNK];
    g_rowptr[i] = rp;
    g_cursor[i] = rp;
}

__global__ void fill_kernel(const int* __restrict__ ei32) {
    int e = blockIdx.x * blockDim.x + threadIdx.x;
    if (e >= EE) return;
    int is64 = g_is64;
    int s = is64 ? ei32[2 * (long long)e] : ei32[e];
    int d = is64 ? ei32[2 * ((long long)EE + e)] : ei32[EE + e];
    s = min(max(s, 0), NN - 1);
    d = min(max(d, 0), NN - 1);
    int pos = atomicAdd(&g_cursor[d], 1);
    g_col[pos] = s;
}

// Prep both W: split fp32 into bf16 hi/lo, row-major [k][n]
__global__ void prepw_kernel(const float* __restrict__ W1,
                             const float* __restrict__ W2) {
    int e = blockIdx.x * blockDim.x + threadIdx.x;
    if (e >= 16384) return;
    float v1 = W1[e];
    __nv_bfloat16 h1 = __float2bfloat16(v1);
    g_wh1[e] = h1;
    g_wl1[e] = __float2bfloat16(v1 - __bfloat162float(h1));
    float v2 = W2[e];
    __nv_bfloat16 h2 = __float2bfloat16(v2);
    g_wh2[e] = h2;
    g_wl2[e] = __float2bfloat16(v2 - __bfloat162float(h2));
}

// ---------------------------------------------------------------------------
// Shared GEMM pieces (512 threads, 16 warps 4x4, 128x128 tile)
// ---------------------------------------------------------------------------
__device__ __forceinline__ void stage_B(__nv_bfloat16* sBh, __nv_bfloat16* sBl,
                                        const __nv_bfloat16* wh,
                                        const __nv_bfloat16* wl, int tid) {
    #pragma unroll
    for (int it = 0; it < 4; it++) {
        int idx = it * 512 + tid;         // 2048 uint4 per array
        int k = idx >> 4;
        int part = idx & 15;
        uint4 vh = ((const uint4*)wh)[idx];
        uint4 vl = ((const uint4*)wl)[idx];
        int off = k * SA + part * 8;
        *(uint4*)(sBh + off) = vh;
        *(uint4*)(sBl + off) = vl;
    }
}

// Full MMA + fp16 epilogue: hout[m,:] = fp16(dinv[m] * A@B)
__device__ __forceinline__ void mma_tile(uint32_t baseAh, uint32_t baseAl,
                                         uint32_t baseBh, uint32_t baseBl,
                                         int wid, int lane, int row0,
                                         __half* hout) {
    int warp_m = wid & 3;
    int warp_n = wid >> 2;

    float acc[2][4][4];
    #pragma unroll
    for (int i = 0; i < 2; i++)
        #pragma unroll
        for (int j = 0; j < 4; j++)
            #pragma unroll
            for (int q = 0; q < 4; q++) acc[i][j][q] = 0.0f;

    int a_row = warp_m * 32 + (lane & 15);
    int a_kadd = (lane >> 4) * 8;
    int b_krow = (lane & 7) + ((lane >> 3) & 1) * 8;
    int b_ncol0 = warp_n * 32 + (lane >> 4) * 8;

    #pragma unroll
    for (int ks = 0; ks < 8; ks++) {
        int k0 = ks * 16;
        uint32_t ah[2][4], al[2][4];
        #pragma unroll
        for (int mt = 0; mt < 2; mt++) {
            uint32_t off = (uint32_t)((a_row + mt * 16) * SA + k0 + a_kadd) * 2;
            ldmatrix_x4(ah[mt], baseAh + off);
            ldmatrix_x4(al[mt], baseAl + off);
        }
        uint32_t bh[4][2], bl[4][2];
        #pragma unroll
        for (int np = 0; np < 2; np++) {
            uint32_t off = (uint32_t)((k0 + b_krow) * SA + b_ncol0 + np * 16) * 2;
            uint32_t t4[4];
            ldmatrix_x4_t(t4, baseBh + off);
            bh[np * 2 + 0][0] = t4[0]; bh[np * 2 + 0][1] = t4[1];
            bh[np * 2 + 1][0] = t4[2]; bh[np * 2 + 1][1] = t4[3];
            ldmatrix_x4_t(t4, baseBl + off);
            bl[np * 2 + 0][0] = t4[0]; bl[np * 2 + 0][1] = t4[1];
            bl[np * 2 + 1][0] = t4[2]; bl[np * 2 + 1][1] = t4[3];
        }
        #pragma unroll
        for (int mt = 0; mt < 2; mt++)
            #pragma unroll
            for (int nt = 0; nt < 4; nt++) {
                mma_bf16(acc[mt][nt], ah[mt], bh[nt]);
                mma_bf16(acc[mt][nt], al[mt], bh[nt]);
                mma_bf16(acc[mt][nt], ah[mt], bl[nt]);
            }
    }

    #pragma unroll
    for (int mt = 0; mt < 2; mt++) {
        int r_lo = row0 + warp_m * 32 + mt * 16 + (lane >> 2);
        int r_hi = r_lo + 8;
        float dv_lo = (r_lo < NN) ? g_dinv[r_lo] : 0.0f;
        float dv_hi = (r_hi < NN) ? g_dinv[r_hi] : 0.0f;
        #pragma unroll
        for (int nt = 0; nt < 4; nt++) {
            int col = warp_n * 32 + nt * 8 + (lane & 3) * 2;
            if (r_lo < NN)
                *(__half2*)(hout + (size_t)r_lo * D + col) =
                    __floats2half2_rn(acc[mt][nt][0] * dv_lo,
                                      acc[mt][nt][1] * dv_lo);
            if (r_hi < NN)
                *(__half2*)(hout + (size_t)r_hi * D + col) =
                    __floats2half2_rn(acc[mt][nt][2] * dv_hi,
                                      acc[mt][nt][3] * dv_hi);
        }
    }
}

// fp16 row accumulate: acc += hbuf[s][lane*4 .. lane*4+3]
__device__ __forceinline__ void add_row16(float4& acc, const __half* hbuf,
                                          int s, int lane) {
    uint2 raw = *(const uint2*)(hbuf + (size_t)s * D + lane * 4);
    __half2 p0 = *reinterpret_cast<const __half2*>(&raw.x);
    __half2 p1 = *reinterpret_cast<const __half2*>(&raw.y);
    float2 f0 = __half22float2(p0);
    float2 f1 = __half22float2(p1);
    acc.x += f0.x; acc.y += f0.y; acc.z += f1.x; acc.w += f1.y;
}

// Warp-per-node CSR gather core: returns acc = self + sum of neighbor rows
__device__ __forceinline__ float4 gather_core(const __half* hbuf, int node,
                                              int lane) {
    int beg = g_rowptr[node];
    int end = g_rowptr[node + 1];
    float4 acc = make_float4(0.f, 0.f, 0.f, 0.f);
    add_row16(acc, hbuf, node, lane);   // self loop
    for (int j = beg; j < end; j += 32) {
        int e = j + lane;
        int c = (e < end) ? __ldg(&g_col[e]) : 0;
        int m = min(32, end - j);
        int t = 0;
        for (; t + 8 <= m; t += 8) {
            int s0 = __shfl_sync(0xffffffffu, c, t + 0);
            int s1 = __shfl_sync(0xffffffffu, c, t + 1);
            int s2 = __shfl_sync(0xffffffffu, c, t + 2);
            int s3 = __shfl_sync(0xffffffffu, c, t + 3);
            int s4 = __shfl_sync(0xffffffffu, c, t + 4);
            int s5 = __shfl_sync(0xffffffffu, c, t + 5);
            int s6 = __shfl_sync(0xffffffffu, c, t + 6);
            int s7 = __shfl_sync(0xffffffffu, c, t + 7);
            add_row16(acc, hbuf, s0, lane); add_row16(acc, hbuf, s1, lane);
            add_row16(acc, hbuf, s2, lane); add_row16(acc, hbuf, s3, lane);
            add_row16(acc, hbuf, s4, lane); add_row16(acc, hbuf, s5, lane);
            add_row16(acc, hbuf, s6, lane); add_row16(acc, hbuf, s7, lane);
        }
        for (; t < m; t++) {
            int s = __shfl_sync(0xffffffffu, c, t);
            add_row16(acc, hbuf, s, lane);
        }
    }
    return acc;
}

// ---------------------------------------------------------------------------
// GEMM layer 1: A staged from fp32 X, B = W1 -> g_h16 = fp16(dinv * X@W1)
// ---------------------------------------------------------------------------
__global__ void __launch_bounds__(512)
gemm1_kernel(const float* __restrict__ X) {
    extern __shared__ char dsm[];
    __nv_bfloat16* sAh = (__nv_bfloat16*)dsm;
    __nv_bfloat16* sAl = (__nv_bfloat16*)(dsm + A_BYTES);
    __nv_bfloat16* sBh = (__nv_bfloat16*)(dsm + 2 * A_BYTES);
    __nv_bfloat16* sBl = (__nv_bfloat16*)(dsm + 3 * A_BYTES);

    int tid = threadIdx.x;
    int wid = tid >> 5;
    int lane = tid & 31;
    int row0 = blockIdx.x * 128;

    #pragma unroll
    for (int it = 0; it < 8; it++) {
        int f = it * 512 + tid;
        int r = f >> 5;
        int p4 = f & 31;
        int gr = row0 + r;
        float4 v = make_float4(0.f, 0.f, 0.f, 0.f);
        if (gr < NN) v = *(const float4*)(X + (size_t)gr * D + p4 * 4);
        uint2 ph, pl;
        split_bf16(v, ph, pl);
        int off = r * SA + p4 * 4;
        *(uint2*)(sAh + off) = ph;
        *(uint2*)(sAl + off) = pl;
    }
    stage_B(sBh, sBl, g_wh1, g_wl1, tid);
    __syncthreads();

    uint32_t baseAh = smem_u32(sAh);
    mma_tile(baseAh, baseAh + A_BYTES, baseAh + 2 * A_BYTES,
             baseAh + 3 * A_BYTES, wid, lane, row0, g_h16);
}

// ---------------------------------------------------------------------------
// Gather layer 1 (sliced): x2 = relu(dinv*(self+nbrs) + b1) as bf16 hi/lo
// over nodes [base, base+cnt)
// ---------------------------------------------------------------------------
__global__ void __launch_bounds__(256)
gather1_kernel(const float* __restrict__ b1, int base, int cnt) {
    int warp = (blockIdx.x * blockDim.x + threadIdx.x) >> 5;
    int lane = threadIdx.x & 31;
    if (warp >= cnt) return;
    int node = base + warp;

    float4 acc = gather_core(g_h16, node, lane);

    float dv = g_dinv[node];
    float4 bb = *(const float4*)(b1 + lane * 4);
    float4 x;
    x.x = fmaxf(acc.x * dv + bb.x, 0.f);
    x.y = fmaxf(acc.y * dv + bb.y, 0.f);
    x.z = fmaxf(acc.z * dv + bb.z, 0.f);
    x.w = fmaxf(acc.w * dv + bb.w, 0.f);

    uint2 ph, pl;
    split_bf16(x, ph, pl);
    *(uint2*)(g_x2h + (size_t)node * D + lane * 4) = ph;
    *(uint2*)(g_x2l + (size_t)node * D + lane * 4) = pl;
}

// ---------------------------------------------------------------------------
// GEMM layer 2 (sliced): A staged from bf16 hi/lo x2 rows [base + bid*128 ...)
// -> g_h16b.  Only reads its own 128 rows of x2.
// ---------------------------------------------------------------------------
__global__ void __launch_bounds__(512)
gemm2_kernel(int base, int limit) {
    extern __shared__ char dsm[];
    __nv_bfloat16* sAh = (__nv_bfloat16*)dsm;
    __nv_bfloat16* sAl = (__nv_bfloat16*)(dsm + A_BYTES);
    __nv_bfloat16* sBh = (__nv_bfloat16*)(dsm + 2 * A_BYTES);
    __nv_bfloat16* sBl = (__nv_bfloat16*)(dsm + 3 * A_BYTES);

    int tid = threadIdx.x;
    int wid = tid >> 5;
    int lane = tid & 31;
    int row0 = base + blockIdx.x * 128;

    #pragma unroll
    for (int it = 0; it < 8; it++) {
        int f = it * 512 + tid;           // 4096 uint2 slots
        int r = f >> 5;
        int p4 = f & 31;
        int gr = row0 + r;
        uint2 vh = make_uint2(0u, 0u), vl = make_uint2(0u, 0u);
        if (gr < limit) {
            vh = *(const uint2*)(g_x2h + (size_t)gr * D + p4 * 4);
            vl = *(const uint2*)(g_x2l + (size_t)gr * D + p4 * 4);
        }
        int off = r * SA + p4 * 4;
        *(uint2*)(sAh + off) = vh;
        *(uint2*)(sAl + off) = vl;
    }
    stage_B(sBh, sBl, g_wh2, g_wl2, tid);
    __syncthreads();

    uint32_t baseAh = smem_u32(sAh);
    // mma_tile guards stores with row < NN; rows >= limit within this slice
    // belong to the next slice and must NOT be written -> pass limit via
    // clamping: rows in [limit, NN) get dinv but their A rows were zeroed,
    // producing h = dinv*0 = 0 writes... must avoid overwriting valid data.
    // Slice bases are multiples of SLICE_N; tiles cover [base, base+196*128)
    // = [base, base+25088) which can exceed base+SLICE_N by 88 rows.
    // Guard: skip epilogue rows >= limit by zeroing dinv contribution is NOT
    // enough (would write zeros). Instead mma_tile writes only rows < NN;
    // we prevent overlap by passing limit as the effective NN for this call.
    mma_tile(baseAh, baseAh + A_BYTES, baseAh + 2 * A_BYTES,
             baseAh + 3 * A_BYTES, wid, lane, row0 - (row0 + 0 >= limit ? 0 : 0),
             g_h16b);
}

// ---------------------------------------------------------------------------
// Final gather: out = (self+nbrs)*dinv + b2, fp32
// ---------------------------------------------------------------------------
__global__ void __launch_bounds__(256)
gather2_kernel(const float* __restrict__ b2, float* __restrict__ out) {
    int warp = (blockIdx.x * blockDim.x + threadIdx.x) >> 5;
    int lane = threadIdx.x & 31;
    if (warp >= NN) return;
    int node = warp;

    float4 acc = gather_core(g_h16b, node, lane);

    float sc = g_dinv[node];
    float4 bb = *(const float4*)(b2 + lane * 4);
    float4 r;
    r.x = acc.x * sc + bb.x;
    r.y = acc.y * sc + bb.y;
    r.z = acc.z * sc + bb.z;
    r.w = acc.w * sc + bb.w;
    *(float4*)(out + (size_t)node * D + lane * 4) = r;
}

// ---------------------------------------------------------------------------
// Launch — kernel launches + captured event fork/join (graph-capture safe;
// stream/events created on the FIRST call, which the harness runs uncaptured)
// ---------------------------------------------------------------------------
extern "C" void kernel_launch(void* const* d_in, const int* in_sizes, int n_in,
                              void* d_out, int out_size) {
    const float* x  = (const float*)d_in[0];
    const int*   ei = (const int*)d_in[1];
    const float* W1 = (const float*)d_in[2];
    const float* b1 = (const float*)d_in[3];
    const float* W2 = (const float*)d_in[4];
    const float* b2 = (const float*)d_in[5];
    float* out = (float*)d_out;

    static cudaStream_t s2 = nullptr;
    static cudaEvent_t evFork = nullptr, evG1 = nullptr, evDone = nullptr;
    static cudaEvent_t evS[NSLICE] = {};
    if (!s2) {
        cudaFuncSetAttribute(gemm1_kernel,
                             cudaFuncAttributeMaxDynamicSharedMemorySize,
                             GEMM_DSMEM);
        cudaFuncSetAttribute(gemm2_kernel,
                             cudaFuncAttributeMaxDynamicSharedMemorySize,
                             GEMM_DSMEM);
        cudaStreamCreateWithFlags(&s2, cudaStreamNonBlocking);
        cudaEventCreateWithFlags(&evFork, cudaEventDisableTiming);
        cudaEventCreateWithFlags(&evG1, cudaEventDisableTiming);
        cudaEventCreateWithFlags(&evDone, cudaEventDisableTiming);
        for (int i = 0; i < NSLICE; i++)
            cudaEventCreateWithFlags(&evS[i], cudaEventDisableTiming);
    }

    const int T = 256;
    const int nb_n = (NN + T - 1) / T;
    const int nb_e = (EE + T - 1) / T;
    const int nb_gath_full = (NN * 32 + T - 1) / T;

    // Main stream: degree histogram
    detect_zero_kernel<<<nb_n, T>>>(ei);
    hist_kernel<<<nb_e, T>>>(ei);

    // Fork: side branch computes prepw + dinv + gemm1 (needs only cnt),
    // while main does scan + fill (CSR build). Disjoint write sets.
    cudaEventRecord(evFork, 0);
    cudaStreamWaitEvent(s2, evFork, 0);

    prepw_kernel<<<64, 256, 0, s2>>>(W1, W2);
    dinv_kernel<<<nb_n, T, 0, s2>>>();
    gemm1_kernel<<<NTILES, 512, GEMM_DSMEM, s2>>>(x);
    cudaEventRecord(evG1, s2);

    // Main: CSR build
    scan1_kernel<<<SCAN_NBLK, SCAN_CHUNK>>>();
    scan2_kernel<<<1, 128>>>();
    scan3_kernel<<<nb_n, T>>>();
    fill_kernel<<<nb_e, T>>>(ei);

    // Join: gather1 needs CSR + g_h16 + dinv
    cudaStreamWaitEvent(0, evG1, 0);

    // Pipelined gather1 (main) / gemm2 (s2) over node slices.
    // Slice bases are multiples of 128 (SLICE_N = 25000 is NOT; round to 128):
    for (int i = 0; i < NSLICE; i++) {
        int base = i * ((SLICE_TILES) * 128);          // 25088-aligned slices
        if (base >= NN) { cudaEventRecord(evS[i], 0); continue; }
        int cnt = min(SLICE_TILES * 128, NN - base);
        int nb_g1 = (cnt * 32 + T - 1) / T;
        gather1_kernel<<<nb_g1, T>>>(b1, base, cnt);
        cudaEventRecord(evS[i], 0);
        cudaStreamWaitEvent(s2, evS[i], 0);
        int ntile = (cnt + 127) / 128;
        gemm2_kernel<<<ntile, 512, GEMM_DSMEM, s2>>>(base, base + cnt);
    }
    cudaEventRecord(evDone, s2);
    cudaStreamWaitEvent(0, evDone, 0);

    gather2_kernel<<<nb_gath_full, T>>>(b2, out);
}

// round 14
// speedup vs baseline: 1.0413x; 1.0318x over previous
#include <cuda_runtime.h>
#include <cuda_bf16.h>
#include <cuda_fp16.h>
#include <cstdint>

#define NN 100000
#define EE 1600000
#define D 128
#define NTILES ((NN + 127) / 128)   // 782

#define SCAN_CHUNK 1024
#define SCAN_NBLK ((NN + SCAN_CHUNK - 1) / SCAN_CHUNK)   // 98

// Padded smem strides (bf16 elements): 272B rows -> conflict-free ldmatrix
#define SA 136
#define A_BYTES (128 * SA * 2)          // 34816
#define GEMM_DSMEM (4 * A_BYTES)        // A_hi, A_lo, B_hi, B_lo = 139264

// ---------------------------------------------------------------------------
// Scratch (static __device__ arrays — allocation is forbidden).
// g_cnt is zero-initialized (BSS) and re-zeroed by gather1 each run.
// ---------------------------------------------------------------------------
__device__ int g_is64;
__device__ __align__(16) int    g_cnt[NN];
__device__ __align__(16) int    g_rowptr[NN + 1];
__device__ __align__(16) int    g_cursor[NN];
__device__ __align__(16) int    g_col[EE];        // src ids grouped by dst
__device__ __align__(16) int    g_part[SCAN_NBLK];
__device__ __align__(16) float  g_dinv[NN];
__device__ __align__(16) __half g_h16[(size_t)NN * D];    // layer-1 h (fp16)
__device__ __align__(16) __half g_h16b[(size_t)NN * D];   // layer-2 h (fp16)
__device__ __align__(16) __nv_bfloat16 g_x2h[(size_t)NN * D];  // x2 hi (bf16)
__device__ __align__(16) __nv_bfloat16 g_x2l[(size_t)NN * D];  // x2 lo (bf16)
__device__ __align__(16) __nv_bfloat16 g_wh1[16384], g_wl1[16384];
__device__ __align__(16) __nv_bfloat16 g_wh2[16384], g_wl2[16384];

// ---------------------------------------------------------------------------
// PTX helpers
// ---------------------------------------------------------------------------
__device__ __forceinline__ uint32_t smem_u32(const void* p) {
    uint32_t a;
    asm("{ .reg .u64 t; cvta.to.shared.u64 t, %1; cvt.u32.u64 %0, t; }"
        : "=r"(a) : "l"(p));
    return a;
}
__device__ __forceinline__ void ldmatrix_x4(uint32_t* r, uint32_t addr) {
    asm volatile("ldmatrix.sync.aligned.m8n8.x4.shared.b16 {%0,%1,%2,%3}, [%4];"
                 : "=r"(r[0]), "=r"(r[1]), "=r"(r[2]), "=r"(r[3]) : "r"(addr));
}
__device__ __forceinline__ void ldmatrix_x4_t(uint32_t* r, uint32_t addr) {
    asm volatile("ldmatrix.sync.aligned.m8n8.x4.trans.shared.b16 {%0,%1,%2,%3}, [%4];"
                 : "=r"(r[0]), "=r"(r[1]), "=r"(r[2]), "=r"(r[3]) : "r"(addr));
}
__device__ __forceinline__ void mma_bf16(float* c, const uint32_t* a,
                                         const uint32_t* b) {
    asm volatile(
        "mma.sync.aligned.m16n8k16.row.col.f32.bf16.bf16.f32 "
        "{%0,%1,%2,%3}, {%4,%5,%6,%7}, {%8,%9}, {%0,%1,%2,%3};"
        : "+f"(c[0]), "+f"(c[1]), "+f"(c[2]), "+f"(c[3])
        : "r"(a[0]), "r"(a[1]), "r"(a[2]), "r"(a[3]), "r"(b[0]), "r"(b[1]));
}

// bf16 hi/lo split of a float4, packed into two uint2
__device__ __forceinline__ void split_bf16(const float4& x, uint2& ph, uint2& pl) {
    __nv_bfloat16 h0 = __float2bfloat16(x.x);
    __nv_bfloat16 h1 = __float2bfloat16(x.y);
    __nv_bfloat16 h2 = __float2bfloat16(x.z);
    __nv_bfloat16 h3 = __float2bfloat16(x.w);
    ph.x = ((uint32_t)__bfloat16_as_ushort(h1) << 16) | __bfloat16_as_ushort(h0);
    ph.y = ((uint32_t)__bfloat16_as_ushort(h3) << 16) | __bfloat16_as_ushort(h2);
    __nv_bfloat16 l0 = __float2bfloat16(x.x - __bfloat162float(h0));
    __nv_bfloat16 l1 = __float2bfloat16(x.y - __bfloat162float(h1));
    __nv_bfloat16 l2 = __float2bfloat16(x.z - __bfloat162float(h2));
    __nv_bfloat16 l3 = __float2bfloat16(x.w - __bfloat162float(h3));
    pl.x = ((uint32_t)__bfloat16_as_ushort(l1) << 16) | __bfloat16_as_ushort(l0);
    pl.y = ((uint32_t)__bfloat16_as_ushort(l3) << 16) | __bfloat16_as_ushort(l2);
}

// ---------------------------------------------------------------------------
// Graph preprocessing
// ---------------------------------------------------------------------------
__global__ void detect_kernel(const int* __restrict__ ei32) {
    if (threadIdx.x == 0) {
        int ored = 0;
        #pragma unroll
        for (int k = 0; k < 32; k++) ored |= ei32[2 * k + 1];
        g_is64 = (ored == 0) ? 1 : 0;
    }
}

__global__ void hist_kernel(const int* __restrict__ ei32) {
    int e = blockIdx.x * blockDim.x + threadIdx.x;
    if (e >= EE) return;
    int is64 = g_is64;
    int d = is64 ? ei32[2 * ((long long)EE + e)] : ei32[EE + e];
    d = min(max(d, 0), NN - 1);
    atomicAdd(&g_cnt[d], 1);
}

// dinv only needs cnt (deg = cnt + 1): runs on the side branch
__global__ void dinv_kernel() {
    int i = blockIdx.x * blockDim.x + threadIdx.x;
    if (i < NN) g_dinv[i] = rsqrtf((float)(g_cnt[i] + 1));
}

__global__ void scan1_kernel() {
    __shared__ int sh[SCAN_CHUNK];
    int i = blockIdx.x * SCAN_CHUNK + threadIdx.x;
    int v = (i < NN) ? g_cnt[i] : 0;
    sh[threadIdx.x] = v;
    __syncthreads();
    #pragma unroll
    for (int off = 1; off < SCAN_CHUNK; off <<= 1) {
        int t = (threadIdx.x >= off) ? sh[threadIdx.x - off] : 0;
        __syncthreads();
        sh[threadIdx.x] += t;
        __syncthreads();
    }
    if (i <= NN - 1) g_rowptr[i] = sh[threadIdx.x] - v;
    if (threadIdx.x == SCAN_CHUNK - 1) g_part[blockIdx.x] = sh[threadIdx.x];
}

// scan3 (scan2 merged in): each block locally sums g_part[0..chunk-1]
__global__ void scan3_kernel() {
    __shared__ int ssum[256];
    int i = blockIdx.x * blockDim.x + threadIdx.x;
    int chunk = (blockIdx.x * blockDim.x) / SCAN_CHUNK;  // block-uniform
    int t = threadIdx.x;
    ssum[t] = (t < chunk) ? g_part[t] : 0;   // chunk <= 97 < 256
    __syncthreads();
    #pragma unroll
    for (int off = 128; off > 0; off >>= 1) {
        if (t < off) ssum[t] += ssum[t + off];
        __syncthreads();
    }
    int base = ssum[0];
    if (i < NN) {
        int rp = g_rowptr[i] + base;
        g_rowptr[i] = rp;
        g_cursor[i] = rp;
    }
    if (i == 0) g_rowptr[NN] = EE;   // every clamped edge contributes 1
}

__global__ void fill_kernel(const int* __restrict__ ei32) {
    int e = blockIdx.x * blockDim.x + threadIdx.x;
    if (e >= EE) return;
    int is64 = g_is64;
    int s = is64 ? ei32[2 * (long long)e] : ei32[e];
    int d = is64 ? ei32[2 * ((long long)EE + e)] : ei32[EE + e];
    s = min(max(s, 0), NN - 1);
    d = min(max(d, 0), NN - 1);
    int pos = atomicAdd(&g_cursor[d], 1);
    g_col[pos] = s;
}

// Prep both W: split fp32 into bf16 hi/lo, row-major [k][n]
__global__ void prepw_kernel(const float* __restrict__ W1,
                             const float* __restrict__ W2) {
    int e = blockIdx.x * blockDim.x + threadIdx.x;
    if (e >= 16384) return;
    float v1 = W1[e];
    __nv_bfloat16 h1 = __float2bfloat16(v1);
    g_wh1[e] = h1;
    g_wl1[e] = __float2bfloat16(v1 - __bfloat162float(h1));
    float v2 = W2[e];
    __nv_bfloat16 h2 = __float2bfloat16(v2);
    g_wh2[e] = h2;
    g_wl2[e] = __float2bfloat16(v2 - __bfloat162float(h2));
}

// ---------------------------------------------------------------------------
// Shared GEMM pieces (512 threads, 16 warps 4x4, 128x128 tile)
// ---------------------------------------------------------------------------
__device__ __forceinline__ void stage_B(__nv_bfloat16* sBh, __nv_bfloat16* sBl,
                                        const __nv_bfloat16* wh,
                                        const __nv_bfloat16* wl, int tid) {
    #pragma unroll
    for (int it = 0; it < 4; it++) {
        int idx = it * 512 + tid;         // 2048 uint4 per array
        int k = idx >> 4;
        int part = idx & 15;
        uint4 vh = ((const uint4*)wh)[idx];
        uint4 vl = ((const uint4*)wl)[idx];
        int off = k * SA + part * 8;
        *(uint4*)(sBh + off) = vh;
        *(uint4*)(sBl + off) = vl;
    }
}

// Full MMA + fp16 epilogue: hout[m,:] = fp16(dinv[m] * A@B)
__device__ __forceinline__ void mma_tile(uint32_t baseAh, uint32_t baseAl,
                                         uint32_t baseBh, uint32_t baseBl,
                                         int wid, int lane, int row0,
                                         __half* hout) {
    int warp_m = wid & 3;
    int warp_n = wid >> 2;

    float acc[2][4][4];
    #pragma unroll
    for (int i = 0; i < 2; i++)
        #pragma unroll
        for (int j = 0; j < 4; j++)
            #pragma unroll
            for (int q = 0; q < 4; q++) acc[i][j][q] = 0.0f;

    int a_row = warp_m * 32 + (lane & 15);
    int a_kadd = (lane >> 4) * 8;
    int b_krow = (lane & 7) + ((lane >> 3) & 1) * 8;
    int b_ncol0 = warp_n * 32 + (lane >> 4) * 8;

    #pragma unroll
    for (int ks = 0; ks < 8; ks++) {
        int k0 = ks * 16;
        uint32_t ah[2][4], al[2][4];
        #pragma unroll
        for (int mt = 0; mt < 2; mt++) {
            uint32_t off = (uint32_t)((a_row + mt * 16) * SA + k0 + a_kadd) * 2;
            ldmatrix_x4(ah[mt], baseAh + off);
            ldmatrix_x4(al[mt], baseAl + off);
        }
        uint32_t bh[4][2], bl[4][2];
        #pragma unroll
        for (int np = 0; np < 2; np++) {
            uint32_t off = (uint32_t)((k0 + b_krow) * SA + b_ncol0 + np * 16) * 2;
            uint32_t t4[4];
            ldmatrix_x4_t(t4, baseBh + off);
            bh[np * 2 + 0][0] = t4[0]; bh[np * 2 + 0][1] = t4[1];
            bh[np * 2 + 1][0] = t4[2]; bh[np * 2 + 1][1] = t4[3];
            ldmatrix_x4_t(t4, baseBl + off);
            bl[np * 2 + 0][0] = t4[0]; bl[np * 2 + 0][1] = t4[1];
            bl[np * 2 + 1][0] = t4[2]; bl[np * 2 + 1][1] = t4[3];
        }
        #pragma unroll
        for (int mt = 0; mt < 2; mt++)
            #pragma unroll
            for (int nt = 0; nt < 4; nt++) {
                mma_bf16(acc[mt][nt], ah[mt], bh[nt]);
                mma_bf16(acc[mt][nt], al[mt], bh[nt]);
                mma_bf16(acc[mt][nt], ah[mt], bl[nt]);
            }
    }

    #pragma unroll
    for (int mt = 0; mt < 2; mt++) {
        int r_lo = row0 + warp_m * 32 + mt * 16 + (lane >> 2);
        int r_hi = r_lo + 8;
        float dv_lo = (r_lo < NN) ? g_dinv[r_lo] : 0.0f;
        float dv_hi = (r_hi < NN) ? g_dinv[r_hi] : 0.0f;
        #pragma unroll
        for (int nt = 0; nt < 4; nt++) {
            int col = warp_n * 32 + nt * 8 + (lane & 3) * 2;
            if (r_lo < NN)
                *(__half2*)(hout + (size_t)r_lo * D + col) =
                    __floats2half2_rn(acc[mt][nt][0] * dv_lo,
                                      acc[mt][nt][1] * dv_lo);
            if (r_hi < NN)
                *(__half2*)(hout + (size_t)r_hi * D + col) =
                    __floats2half2_rn(acc[mt][nt][2] * dv_hi,
                                      acc[mt][nt][3] * dv_hi);
        }
    }
}

// fp16 row accumulate: acc[0..7] += hbuf[s][hl*8 .. hl*8+7]  (uint4 load)
__device__ __forceinline__ void add_row16q(float* acc, const __half* hbuf,
                                           int s, int hl) {
    uint4 raw = *(const uint4*)(hbuf + (size_t)s * D + hl * 8);
    float2 f0 = __half22float2(*reinterpret_cast<const __half2*>(&raw.x));
    float2 f1 = __half22float2(*reinterpret_cast<const __half2*>(&raw.y));
    float2 f2 = __half22float2(*reinterpret_cast<const __half2*>(&raw.z));
    float2 f3 = __half22float2(*reinterpret_cast<const __half2*>(&raw.w));
    acc[0] += f0.x; acc[1] += f0.y; acc[2] += f1.x; acc[3] += f1.y;
    acc[4] += f2.x; acc[5] += f2.y; acc[6] += f3.x; acc[7] += f3.y;
}

// Warp-per-node gather, paired edges: lanes 0-15 take even edges, 16-31 odd
// edges of the SAME node (no imbalance). Each lane loads uint4 (8 halves) of
// cols hl*8..hl*8+7. Final shfl_xor(16) combines the two halves.
// Returns acc[0..7]; valid on ALL lanes after combine.
__device__ __forceinline__ void gather_core_pair(float* acc, const __half* hbuf,
                                                 int node, int half, int hl) {
    int beg = g_rowptr[node];
    int end = g_rowptr[node + 1];
    #pragma unroll
    for (int i = 0; i < 8; i++) acc[i] = 0.0f;
    if (half == 0) add_row16q(acc, hbuf, node, hl);   // self loop (once)

    int lane = (half << 4) + hl;
    for (int j = beg; j < end; j += 32) {
        int e = j + lane;
        int c = (e < end) ? __ldg(&g_col[e]) : 0;
        int m = min(32, end - j);
        int t = 0;
        for (; t + 8 <= m; t += 8) {
            int s0 = __shfl_sync(0xffffffffu, c, t + 0 + half);
            int s1 = __shfl_sync(0xffffffffu, c, t + 2 + half);
            int s2 = __shfl_sync(0xffffffffu, c, t + 4 + half);
            int s3 = __shfl_sync(0xffffffffu, c, t + 6 + half);
            add_row16q(acc, hbuf, s0, hl);
            add_row16q(acc, hbuf, s1, hl);
            add_row16q(acc, hbuf, s2, hl);
            add_row16q(acc, hbuf, s3, hl);
        }
        for (; t < m; t += 2) {
            int s = __shfl_sync(0xffffffffu, c, (t + half) & 31);
            if (t + half < m) add_row16q(acc, hbuf, s, hl);
        }
    }
    // combine even/odd halves
    #pragma unroll
    for (int i = 0; i < 8; i++)
        acc[i] += __shfl_xor_sync(0xffffffffu, acc[i], 16);
}

// ---------------------------------------------------------------------------
// GEMM layer 1: A staged from fp32 X, B = W1 -> g_h16 = fp16(dinv * X@W1)
// ---------------------------------------------------------------------------
__global__ void __launch_bounds__(512)
gemm1_kernel(const float* __restrict__ X) {
    extern __shared__ char dsm[];
    __nv_bfloat16* sAh = (__nv_bfloat16*)dsm;
    __nv_bfloat16* sAl = (__nv_bfloat16*)(dsm + A_BYTES);
    __nv_bfloat16* sBh = (__nv_bfloat16*)(dsm + 2 * A_BYTES);
    __nv_bfloat16* sBl = (__nv_bfloat16*)(dsm + 3 * A_BYTES);

    int tid = threadIdx.x;
    int wid = tid >> 5;
    int lane = tid & 31;
    int row0 = blockIdx.x * 128;

    #pragma unroll
    for (int it = 0; it < 8; it++) {
        int f = it * 512 + tid;
        int r = f >> 5;
        int p4 = f & 31;
        int gr = row0 + r;
        float4 v = make_float4(0.f, 0.f, 0.f, 0.f);
        if (gr < NN) v = *(const float4*)(X + (size_t)gr * D + p4 * 4);
        uint2 ph, pl;
        split_bf16(v, ph, pl);
        int off = r * SA + p4 * 4;
        *(uint2*)(sAh + off) = ph;
        *(uint2*)(sAl + off) = pl;
    }
    stage_B(sBh, sBl, g_wh1, g_wl1, tid);
    __syncthreads();

    uint32_t baseAh = smem_u32(sAh);
    mma_tile(baseAh, baseAh + A_BYTES, baseAh + 2 * A_BYTES,
             baseAh + 3 * A_BYTES, wid, lane, row0, g_h16);
}

// ---------------------------------------------------------------------------
// Gather layer 1: x2 = relu(dinv*(self+nbrs) + b1) as bf16 hi/lo.
// Also re-zeroes g_cnt for the next graph replay.
// ---------------------------------------------------------------------------
__global__ void __launch_bounds__(256)
gather1_kernel(const float* __restrict__ b1) {
    int warp = (blockIdx.x * blockDim.x + threadIdx.x) >> 5;
    int lane = threadIdx.x & 31;
    if (warp >= NN) return;
    int node = warp;
    int half = lane >> 4;
    int hl = lane & 15;

    if (lane == 0) g_cnt[node] = 0;   // reset for next replay

    float acc[8];
    gather_core_pair(acc, g_h16, node, half, hl);

    if (half == 0) {
        float dv = g_dinv[node];
        float4 b_lo = *(const float4*)(b1 + hl * 8);
        float4 b_hi = *(const float4*)(b1 + hl * 8 + 4);
        float4 xa, xb;
        xa.x = fmaxf(acc[0] * dv + b_lo.x, 0.f);
        xa.y = fmaxf(acc[1] * dv + b_lo.y, 0.f);
        xa.z = fmaxf(acc[2] * dv + b_lo.z, 0.f);
        xa.w = fmaxf(acc[3] * dv + b_lo.w, 0.f);
        xb.x = fmaxf(acc[4] * dv + b_hi.x, 0.f);
        xb.y = fmaxf(acc[5] * dv + b_hi.y, 0.f);
        xb.z = fmaxf(acc[6] * dv + b_hi.z, 0.f);
        xb.w = fmaxf(acc[7] * dv + b_hi.w, 0.f);

        uint2 pha, pla, phb, plb;
        split_bf16(xa, pha, pla);
        split_bf16(xb, phb, plb);
        *(uint4*)(g_x2h + (size_t)node * D + hl * 8) =
            make_uint4(pha.x, pha.y, phb.x, phb.y);
        *(uint4*)(g_x2l + (size_t)node * D + hl * 8) =
            make_uint4(pla.x, pla.y, plb.x, plb.y);
    }
}

// ---------------------------------------------------------------------------
// GEMM layer 2: A staged from prepped bf16 hi/lo x2 -> g_h16b
// ---------------------------------------------------------------------------
__global__ void __launch_bounds__(512)
gemm2_kernel() {
    extern __shared__ char dsm[];
    __nv_bfloat16* sAh = (__nv_bfloat16*)dsm;
    __nv_bfloat16* sAl = (__nv_bfloat16*)(dsm + A_BYTES);
    __nv_bfloat16* sBh = (__nv_bfloat16*)(dsm + 2 * A_BYTES);
    __nv_bfloat16* sBl = (__nv_bfloat16*)(dsm + 3 * A_BYTES);

    int tid = threadIdx.x;
    int wid = tid >> 5;
    int lane = tid & 31;
    int row0 = blockIdx.x * 128;

    #pragma unroll
    for (int it = 0; it < 8; it++) {
        int f = it * 512 + tid;           // 4096 uint2 slots
        int r = f >> 5;
        int p4 = f & 31;
        int gr = row0 + r;
        uint2 vh = make_uint2(0u, 0u), vl = make_uint2(0u, 0u);
        if (gr < NN) {
            vh = *(const uint2*)(g_x2h + (size_t)gr * D + p4 * 4);
            vl = *(const uint2*)(g_x2l + (size_t)gr * D + p4 * 4);
        }
        int off = r * SA + p4 * 4;
        *(uint2*)(sAh + off) = vh;
        *(uint2*)(sAl + off) = vl;
    }
    stage_B(sBh, sBl, g_wh2, g_wl2, tid);
    __syncthreads();

    uint32_t baseAh = smem_u32(sAh);
    mma_tile(baseAh, baseAh + A_BYTES, baseAh + 2 * A_BYTES,
             baseAh + 3 * A_BYTES, wid, lane, row0, g_h16b);
}

// ---------------------------------------------------------------------------
// Final gather: out = (self+nbrs)*dinv + b2, fp32
// ---------------------------------------------------------------------------
__global__ void __launch_bounds__(256)
gather2_kernel(const float* __restrict__ b2, float* __restrict__ out) {
    int warp = (blockIdx.x * blockDim.x + threadIdx.x) >> 5;
    int lane = threadIdx.x & 31;
    if (warp >= NN) return;
    int node = warp;
    int half = lane >> 4;
    int hl = lane & 15;

    float acc[8];
    gather_core_pair(acc, g_h16b, node, half, hl);

    if (half == 0) {
        float sc = g_dinv[node];
        float4 b_lo = *(const float4*)(b2 + hl * 8);
        float4 b_hi = *(const float4*)(b2 + hl * 8 + 4);
        float4 ra, rb;
        ra.x = acc[0] * sc + b_lo.x;
        ra.y = acc[1] * sc + b_lo.y;
        ra.z = acc[2] * sc + b_lo.z;
        ra.w = acc[3] * sc + b_lo.w;
        rb.x = acc[4] * sc + b_hi.x;
        rb.y = acc[5] * sc + b_hi.y;
        rb.z = acc[6] * sc + b_hi.z;
        rb.w = acc[7] * sc + b_hi.w;
        *(float4*)(out + (size_t)node * D + hl * 8) = ra;
        *(float4*)(out + (size_t)node * D + hl * 8 + 4) = rb;
    }
}

// ---------------------------------------------------------------------------
// Launch — kernel launches + captured event fork/join (graph-capture safe;
// stream/events created on the FIRST call, which the harness runs uncaptured)
// ---------------------------------------------------------------------------
extern "C" void kernel_launch(void* const* d_in, const int* in_sizes, int n_in,
                              void* d_out, int out_size) {
    const float* x  = (const float*)d_in[0];
    const int*   ei = (const int*)d_in[1];
    const float* W1 = (const float*)d_in[2];
    const float* b1 = (const float*)d_in[3];
    const float* W2 = (const float*)d_in[4];
    const float* b2 = (const float*)d_in[5];
    float* out = (float*)d_out;

    static cudaStream_t s2 = nullptr;
    static cudaEvent_t evFork = nullptr, evJoin = nullptr;
    if (!s2) {
        cudaFuncSetAttribute(gemm1_kernel,
                             cudaFuncAttributeMaxDynamicSharedMemorySize,
                             GEMM_DSMEM);
        cudaFuncSetAttribute(gemm2_kernel,
                             cudaFuncAttributeMaxDynamicSharedMemorySize,
                             GEMM_DSMEM);
        cudaStreamCreateWithFlags(&s2, cudaStreamNonBlocking);
        cudaEventCreateWithFlags(&evFork, cudaEventDisableTiming);
        cudaEventCreateWithFlags(&evJoin, cudaEventDisableTiming);
    }

    const int T = 256;
    const int nb_n    = (NN + T - 1) / T;
    const int nb_e    = (EE + T - 1) / T;
    const int nb_gath = (NN * 32 + T - 1) / T;

    // Main stream: detect width + degree histogram (cnt enters zeroed:
    // BSS-init on first call, re-zeroed by gather1 on every run)
    detect_kernel<<<1, 32>>>(ei);
    hist_kernel<<<nb_e, T>>>(ei);

    // Fork: side branch computes prepw + dinv + gemm1 (needs only cnt),
    // while main does scan + fill (CSR build). Disjoint write sets.
    cudaEventRecord(evFork, 0);
    cudaStreamWaitEvent(s2, evFork, 0);

    prepw_kernel<<<64, 256, 0, s2>>>(W1, W2);
    dinv_kernel<<<nb_n, T, 0, s2>>>();
    gemm1_kernel<<<NTILES, 512, GEMM_DSMEM, s2>>>(x);
    cudaEventRecord(evJoin, s2);

    // Main: CSR build (scan2 merged into scan3)
    scan1_kernel<<<SCAN_NBLK, SCAN_CHUNK>>>();
    scan3_kernel<<<nb_n, T>>>();
    fill_kernel<<<nb_e, T>>>(ei);

    // Join: gather1 needs CSR + g_h16 + dinv
    cudaStreamWaitEvent(0, evJoin, 0);

    gather1_kernel<<<nb_gath, T>>>(b1);
    gemm2_kernel<<<NTILES, 512, GEMM_DSMEM>>>();
    gather2_kernel<<<nb_gath, T>>>(b2, out);
}

// round 15
// speedup vs baseline: 1.0616x; 1.0195x over previous
#include <cuda_runtime.h>
#include <cuda_bf16.h>
#include <cuda_fp16.h>
#include <cstdint>

#define NN 100000
#define EE 1600000
#define D 128
#define NTILES ((NN + 127) / 128)   // 782

#define SCAN_CHUNK 1024
#define SCAN_NBLK ((NN + SCAN_CHUNK - 1) / SCAN_CHUNK)   // 98

// Padded smem strides (bf16 elements): 272B rows -> conflict-free ldmatrix
#define SA 136
#define A_BYTES (128 * SA * 2)          // 34816
#define GEMM_DSMEM (4 * A_BYTES)        // A_hi, A_lo, B_hi, B_lo = 139264

// ---------------------------------------------------------------------------
// Scratch (static __device__ arrays — allocation is forbidden).
// g_cnt is zero-initialized (BSS) and re-zeroed by gather1 each run.
// ---------------------------------------------------------------------------
__device__ int g_is64;
__device__ __align__(16) int    g_cnt[NN];
__device__ __align__(16) int    g_rowptr[NN + 1];
__device__ __align__(16) int    g_cursor[NN];
__device__ __align__(16) int    g_col[EE];        // src ids grouped by dst
__device__ __align__(16) int    g_part[SCAN_NBLK];
__device__ __align__(16) float  g_dinv[NN];
__device__ __align__(16) __half g_h16[(size_t)NN * D];    // layer-1 h (fp16)
__device__ __align__(16) __half g_h16b[(size_t)NN * D];   // layer-2 h (fp16)
__device__ __align__(16) __nv_bfloat16 g_x2h[(size_t)NN * D];  // x2 hi (bf16)
__device__ __align__(16) __nv_bfloat16 g_x2l[(size_t)NN * D];  // x2 lo (bf16)
__device__ __align__(16) __nv_bfloat16 g_wh1[16384], g_wl1[16384];
__device__ __align__(16) __nv_bfloat16 g_wh2[16384], g_wl2[16384];

// ---------------------------------------------------------------------------
// PTX helpers
// ---------------------------------------------------------------------------
__device__ __forceinline__ uint32_t smem_u32(const void* p) {
    uint32_t a;
    asm("{ .reg .u64 t; cvta.to.shared.u64 t, %1; cvt.u32.u64 %0, t; }"
        : "=r"(a) : "l"(p));
    return a;
}
__device__ __forceinline__ void ldmatrix_x4(uint32_t* r, uint32_t addr) {
    asm volatile("ldmatrix.sync.aligned.m8n8.x4.shared.b16 {%0,%1,%2,%3}, [%4];"
                 : "=r"(r[0]), "=r"(r[1]), "=r"(r[2]), "=r"(r[3]) : "r"(addr));
}
__device__ __forceinline__ void ldmatrix_x4_t(uint32_t* r, uint32_t addr) {
    asm volatile("ldmatrix.sync.aligned.m8n8.x4.trans.shared.b16 {%0,%1,%2,%3}, [%4];"
                 : "=r"(r[0]), "=r"(r[1]), "=r"(r[2]), "=r"(r[3]) : "r"(addr));
}
__device__ __forceinline__ void mma_bf16(float* c, const uint32_t* a,
                                         const uint32_t* b) {
    asm volatile(
        "mma.sync.aligned.m16n8k16.row.col.f32.bf16.bf16.f32 "
        "{%0,%1,%2,%3}, {%4,%5,%6,%7}, {%8,%9}, {%0,%1,%2,%3};"
        : "+f"(c[0]), "+f"(c[1]), "+f"(c[2]), "+f"(c[3])
        : "r"(a[0]), "r"(a[1]), "r"(a[2]), "r"(a[3]), "r"(b[0]), "r"(b[1]));
}

// bf16 hi/lo split of a float4, packed into two uint2
__device__ __forceinline__ void split_bf16(const float4& x, uint2& ph, uint2& pl) {
    __nv_bfloat16 h0 = __float2bfloat16(x.x);
    __nv_bfloat16 h1 = __float2bfloat16(x.y);
    __nv_bfloat16 h2 = __float2bfloat16(x.z);
    __nv_bfloat16 h3 = __float2bfloat16(x.w);
    ph.x = ((uint32_t)__bfloat16_as_ushort(h1) << 16) | __bfloat16_as_ushort(h0);
    ph.y = ((uint32_t)__bfloat16_as_ushort(h3) << 16) | __bfloat16_as_ushort(h2);
    __nv_bfloat16 l0 = __float2bfloat16(x.x - __bfloat162float(h0));
    __nv_bfloat16 l1 = __float2bfloat16(x.y - __bfloat162float(h1));
    __nv_bfloat16 l2 = __float2bfloat16(x.z - __bfloat162float(h2));
    __nv_bfloat16 l3 = __float2bfloat16(x.w - __bfloat162float(h3));
    pl.x = ((uint32_t)__bfloat16_as_ushort(l1) << 16) | __bfloat16_as_ushort(l0);
    pl.y = ((uint32_t)__bfloat16_as_ushort(l3) << 16) | __bfloat16_as_ushort(l2);
}

// ---------------------------------------------------------------------------
// Graph preprocessing
// ---------------------------------------------------------------------------
__global__ void detect_kernel(const int* __restrict__ ei32) {
    if (threadIdx.x == 0) {
        int ored = 0;
        #pragma unroll
        for (int k = 0; k < 32; k++) ored |= ei32[2 * k + 1];
        g_is64 = (ored == 0) ? 1 : 0;
    }
}

__global__ void hist_kernel(const int* __restrict__ ei32) {
    int e = blockIdx.x * blockDim.x + threadIdx.x;
    if (e >= EE) return;
    int is64 = g_is64;
    int d = is64 ? ei32[2 * ((long long)EE + e)] : ei32[EE + e];
    d = min(max(d, 0), NN - 1);
    atomicAdd(&g_cnt[d], 1);
}

// dinv only needs cnt (deg = cnt + 1): runs on the side branch
__global__ void dinv_kernel() {
    int i = blockIdx.x * blockDim.x + threadIdx.x;
    if (i < NN) g_dinv[i] = rsqrtf((float)(g_cnt[i] + 1));
}

__global__ void scan1_kernel() {
    __shared__ int sh[SCAN_CHUNK];
    int i = blockIdx.x * SCAN_CHUNK + threadIdx.x;
    int v = (i < NN) ? g_cnt[i] : 0;
    sh[threadIdx.x] = v;
    __syncthreads();
    #pragma unroll
    for (int off = 1; off < SCAN_CHUNK; off <<= 1) {
        int t = (threadIdx.x >= off) ? sh[threadIdx.x - off] : 0;
        __syncthreads();
        sh[threadIdx.x] += t;
        __syncthreads();
    }
    if (i <= NN - 1) g_rowptr[i] = sh[threadIdx.x] - v;
    if (threadIdx.x == SCAN_CHUNK - 1) g_part[blockIdx.x] = sh[threadIdx.x];
}

// scan3 (scan2 merged in): each block locally sums g_part[0..chunk-1]
__global__ void scan3_kernel() {
    __shared__ int ssum[256];
    int i = blockIdx.x * blockDim.x + threadIdx.x;
    int chunk = (blockIdx.x * blockDim.x) / SCAN_CHUNK;  // block-uniform
    int t = threadIdx.x;
    ssum[t] = (t < chunk) ? g_part[t] : 0;   // chunk <= 97 < 256
    __syncthreads();
    #pragma unroll
    for (int off = 128; off > 0; off >>= 1) {
        if (t < off) ssum[t] += ssum[t + off];
        __syncthreads();
    }
    int base = ssum[0];
    if (i < NN) {
        int rp = g_rowptr[i] + base;
        g_rowptr[i] = rp;
        g_cursor[i] = rp;
    }
    if (i == 0) g_rowptr[NN] = EE;   // every clamped edge contributes 1
}

__global__ void fill_kernel(const int* __restrict__ ei32) {
    int e = blockIdx.x * blockDim.x + threadIdx.x;
    if (e >= EE) return;
    int is64 = g_is64;
    int s = is64 ? ei32[2 * (long long)e] : ei32[e];
    int d = is64 ? ei32[2 * ((long long)EE + e)] : ei32[EE + e];
    s = min(max(s, 0), NN - 1);
    d = min(max(d, 0), NN - 1);
    int pos = atomicAdd(&g_cursor[d], 1);
    g_col[pos] = s;
}

// Prep both W: split fp32 into bf16 hi/lo, row-major [k][n]
__global__ void prepw_kernel(const float* __restrict__ W1,
                             const float* __restrict__ W2) {
    int e = blockIdx.x * blockDim.x + threadIdx.x;
    if (e >= 16384) return;
    float v1 = W1[e];
    __nv_bfloat16 h1 = __float2bfloat16(v1);
    g_wh1[e] = h1;
    g_wl1[e] = __float2bfloat16(v1 - __bfloat162float(h1));
    float v2 = W2[e];
    __nv_bfloat16 h2 = __float2bfloat16(v2);
    g_wh2[e] = h2;
    g_wl2[e] = __float2bfloat16(v2 - __bfloat162float(h2));
}

// ---------------------------------------------------------------------------
// Shared GEMM pieces (512 threads, 16 warps 4x4, 128x128 tile)
// ---------------------------------------------------------------------------
__device__ __forceinline__ void stage_B(__nv_bfloat16* sBh, __nv_bfloat16* sBl,
                                        const __nv_bfloat16* wh,
                                        const __nv_bfloat16* wl, int tid) {
    #pragma unroll
    for (int it = 0; it < 4; it++) {
        int idx = it * 512 + tid;         // 2048 uint4 per array
        int k = idx >> 4;
        int part = idx & 15;
        uint4 vh = ((const uint4*)wh)[idx];
        uint4 vl = ((const uint4*)wl)[idx];
        int off = k * SA + part * 8;
        *(uint4*)(sBh + off) = vh;
        *(uint4*)(sBl + off) = vl;
    }
}

// Full MMA + fp16 epilogue: hout[m,:] = fp16(dinv[m] * A@B)
__device__ __forceinline__ void mma_tile(uint32_t baseAh, uint32_t baseAl,
                                         uint32_t baseBh, uint32_t baseBl,
                                         int wid, int lane, int row0,
                                         __half* hout) {
    int warp_m = wid & 3;
    int warp_n = wid >> 2;

    float acc[2][4][4];
    #pragma unroll
    for (int i = 0; i < 2; i++)
        #pragma unroll
        for (int j = 0; j < 4; j++)
            #pragma unroll
            for (int q = 0; q < 4; q++) acc[i][j][q] = 0.0f;

    int a_row = warp_m * 32 + (lane & 15);
    int a_kadd = (lane >> 4) * 8;
    int b_krow = (lane & 7) + ((lane >> 3) & 1) * 8;
    int b_ncol0 = warp_n * 32 + (lane >> 4) * 8;

    #pragma unroll
    for (int ks = 0; ks < 8; ks++) {
        int k0 = ks * 16;
        uint32_t ah[2][4], al[2][4];
        #pragma unroll
        for (int mt = 0; mt < 2; mt++) {
            uint32_t off = (uint32_t)((a_row + mt * 16) * SA + k0 + a_kadd) * 2;
            ldmatrix_x4(ah[mt], baseAh + off);
            ldmatrix_x4(al[mt], baseAl + off);
        }
        uint32_t bh[4][2], bl[4][2];
        #pragma unroll
        for (int np = 0; np < 2; np++) {
            uint32_t off = (uint32_t)((k0 + b_krow) * SA + b_ncol0 + np * 16) * 2;
            uint32_t t4[4];
            ldmatrix_x4_t(t4, baseBh + off);
            bh[np * 2 + 0][0] = t4[0]; bh[np * 2 + 0][1] = t4[1];
            bh[np * 2 + 1][0] = t4[2]; bh[np * 2 + 1][1] = t4[3];
            ldmatrix_x4_t(t4, baseBl + off);
            bl[np * 2 + 0][0] = t4[0]; bl[np * 2 + 0][1] = t4[1];
            bl[np * 2 + 1][0] = t4[2]; bl[np * 2 + 1][1] = t4[3];
        }
        #pragma unroll
        for (int mt = 0; mt < 2; mt++)
            #pragma unroll
            for (int nt = 0; nt < 4; nt++) {
                mma_bf16(acc[mt][nt], ah[mt], bh[nt]);
                mma_bf16(acc[mt][nt], al[mt], bh[nt]);
                mma_bf16(acc[mt][nt], ah[mt], bl[nt]);
            }
    }

    #pragma unroll
    for (int mt = 0; mt < 2; mt++) {
        int r_lo = row0 + warp_m * 32 + mt * 16 + (lane >> 2);
        int r_hi = r_lo + 8;
        float dv_lo = (r_lo < NN) ? g_dinv[r_lo] : 0.0f;
        float dv_hi = (r_hi < NN) ? g_dinv[r_hi] : 0.0f;
        #pragma unroll
        for (int nt = 0; nt < 4; nt++) {
            int col = warp_n * 32 + nt * 8 + (lane & 3) * 2;
            if (r_lo < NN)
                *(__half2*)(hout + (size_t)r_lo * D + col) =
                    __floats2half2_rn(acc[mt][nt][0] * dv_lo,
                                      acc[mt][nt][1] * dv_lo);
            if (r_hi < NN)
                *(__half2*)(hout + (size_t)r_hi * D + col) =
                    __floats2half2_rn(acc[mt][nt][2] * dv_hi,
                                      acc[mt][nt][3] * dv_hi);
        }
    }
}

// fp16 row accumulate: acc += hbuf[s][lane*4 .. lane*4+3]
__device__ __forceinline__ void add_row16(float4& acc, const __half* hbuf,
                                          int s, int lane) {
    uint2 raw = *(const uint2*)(hbuf + (size_t)s * D + lane * 4);
    __half2 p0 = *reinterpret_cast<const __half2*>(&raw.x);
    __half2 p1 = *reinterpret_cast<const __half2*>(&raw.y);
    float2 f0 = __half22float2(p0);
    float2 f1 = __half22float2(p1);
    acc.x += f0.x; acc.y += f0.y; acc.z += f1.x; acc.w += f1.y;
}

// Warp-per-node CSR gather core (R11 config — best measured)
__device__ __forceinline__ float4 gather_core(const __half* hbuf, int node,
                                              int lane) {
    int beg = g_rowptr[node];
    int end = g_rowptr[node + 1];
    float4 acc = make_float4(0.f, 0.f, 0.f, 0.f);
    add_row16(acc, hbuf, node, lane);   // self loop
    for (int j = beg; j < end; j += 32) {
        int e = j + lane;
        int c = (e < end) ? __ldg(&g_col[e]) : 0;
        int m = min(32, end - j);
        int t = 0;
        for (; t + 8 <= m; t += 8) {
            int s0 = __shfl_sync(0xffffffffu, c, t + 0);
            int s1 = __shfl_sync(0xffffffffu, c, t + 1);
            int s2 = __shfl_sync(0xffffffffu, c, t + 2);
            int s3 = __shfl_sync(0xffffffffu, c, t + 3);
            int s4 = __shfl_sync(0xffffffffu, c, t + 4);
            int s5 = __shfl_sync(0xffffffffu, c, t + 5);
            int s6 = __shfl_sync(0xffffffffu, c, t + 6);
            int s7 = __shfl_sync(0xffffffffu, c, t + 7);
            add_row16(acc, hbuf, s0, lane); add_row16(acc, hbuf, s1, lane);
            add_row16(acc, hbuf, s2, lane); add_row16(acc, hbuf, s3, lane);
            add_row16(acc, hbuf, s4, lane); add_row16(acc, hbuf, s5, lane);
            add_row16(acc, hbuf, s6, lane); add_row16(acc, hbuf, s7, lane);
        }
        for (; t < m; t++) {
            int s = __shfl_sync(0xffffffffu, c, t);
            add_row16(acc, hbuf, s, lane);
        }
    }
    return acc;
}

// ---------------------------------------------------------------------------
// GEMM layer 1: A staged from fp32 X, B = W1 -> g_h16 = fp16(dinv * X@W1)
// ---------------------------------------------------------------------------
__global__ void __launch_bounds__(512)
gemm1_kernel(const float* __restrict__ X) {
    extern __shared__ char dsm[];
    __nv_bfloat16* sAh = (__nv_bfloat16*)dsm;
    __nv_bfloat16* sAl = (__nv_bfloat16*)(dsm + A_BYTES);
    __nv_bfloat16* sBh = (__nv_bfloat16*)(dsm + 2 * A_BYTES);
    __nv_bfloat16* sBl = (__nv_bfloat16*)(dsm + 3 * A_BYTES);

    int tid = threadIdx.x;
    int wid = tid >> 5;
    int lane = tid & 31;
    int row0 = blockIdx.x * 128;

    #pragma unroll
    for (int it = 0; it < 8; it++) {
        int f = it * 512 + tid;
        int r = f >> 5;
        int p4 = f & 31;
        int gr = row0 + r;
        float4 v = make_float4(0.f, 0.f, 0.f, 0.f);
        if (gr < NN) v = *(const float4*)(X + (size_t)gr * D + p4 * 4);
        uint2 ph, pl;
        split_bf16(v, ph, pl);
        int off = r * SA + p4 * 4;
        *(uint2*)(sAh + off) = ph;
        *(uint2*)(sAl + off) = pl;
    }
    stage_B(sBh, sBl, g_wh1, g_wl1, tid);
    __syncthreads();

    uint32_t baseAh = smem_u32(sAh);
    mma_tile(baseAh, baseAh + A_BYTES, baseAh + 2 * A_BYTES,
             baseAh + 3 * A_BYTES, wid, lane, row0, g_h16);
}

// ---------------------------------------------------------------------------
// Gather layer 1: x2 = relu(dinv*(self+nbrs) + b1) as bf16 hi/lo.
// Also re-zeroes g_cnt for the next graph replay.
// ---------------------------------------------------------------------------
__global__ void __launch_bounds__(256)
gather1_kernel(const float* __restrict__ b1) {
    int warp = (blockIdx.x * blockDim.x + threadIdx.x) >> 5;
    int lane = threadIdx.x & 31;
    if (warp >= NN) return;
    int node = warp;

    if (lane == 0) g_cnt[node] = 0;   // reset for next replay

    float4 acc = gather_core(g_h16, node, lane);

    float dv = g_dinv[node];
    float4 bb = *(const float4*)(b1 + lane * 4);
    float4 x;
    x.x = fmaxf(acc.x * dv + bb.x, 0.f);
    x.y = fmaxf(acc.y * dv + bb.y, 0.f);
    x.z = fmaxf(acc.z * dv + bb.z, 0.f);
    x.w = fmaxf(acc.w * dv + bb.w, 0.f);

    uint2 ph, pl;
    split_bf16(x, ph, pl);
    *(uint2*)(g_x2h + (size_t)node * D + lane * 4) = ph;
    *(uint2*)(g_x2l + (size_t)node * D + lane * 4) = pl;
}

// ---------------------------------------------------------------------------
// GEMM layer 2: A staged from prepped bf16 hi/lo x2 -> g_h16b
// ---------------------------------------------------------------------------
__global__ void __launch_bounds__(512)
gemm2_kernel() {
    extern __shared__ char dsm[];
    __nv_bfloat16* sAh = (__nv_bfloat16*)dsm;
    __nv_bfloat16* sAl = (__nv_bfloat16*)(dsm + A_BYTES);
    __nv_bfloat16* sBh = (__nv_bfloat16*)(dsm + 2 * A_BYTES);
    __nv_bfloat16* sBl = (__nv_bfloat16*)(dsm + 3 * A_BYTES);

    int tid = threadIdx.x;
    int wid = tid >> 5;
    int lane = tid & 31;
    int row0 = blockIdx.x * 128;

    #pragma unroll
    for (int it = 0; it < 8; it++) {
        int f = it * 512 + tid;           // 4096 uint2 slots
        int r = f >> 5;
        int p4 = f & 31;
        int gr = row0 + r;
        uint2 vh = make_uint2(0u, 0u), vl = make_uint2(0u, 0u);
        if (gr < NN) {
            vh = *(const uint2*)(g_x2h + (size_t)gr * D + p4 * 4);
            vl = *(const uint2*)(g_x2l + (size_t)gr * D + p4 * 4);
        }
        int off = r * SA + p4 * 4;
        *(uint2*)(sAh + off) = vh;
        *(uint2*)(sAl + off) = vl;
    }
    stage_B(sBh, sBl, g_wh2, g_wl2, tid);
    __syncthreads();

    uint32_t baseAh = smem_u32(sAh);
    mma_tile(baseAh, baseAh + A_BYTES, baseAh + 2 * A_BYTES,
             baseAh + 3 * A_BYTES, wid, lane, row0, g_h16b);
}

// ---------------------------------------------------------------------------
// Final gather: out = (self+nbrs)*dinv + b2, fp32
// ---------------------------------------------------------------------------
__global__ void __launch_bounds__(256)
gather2_kernel(const float* __restrict__ b2, float* __restrict__ out) {
    int warp = (blockIdx.x * blockDim.x + threadIdx.x) >> 5;
    int lane = threadIdx.x & 31;
    if (warp >= NN) return;
    int node = warp;

    float4 acc = gather_core(g_h16b, node, lane);

    float sc = g_dinv[node];
    float4 bb = *(const float4*)(b2 + lane * 4);
    float4 r;
    r.x = acc.x * sc + bb.x;
    r.y = acc.y * sc + bb.y;
    r.z = acc.z * sc + bb.z;
    r.w = acc.w * sc + bb.w;
    *(float4*)(out + (size_t)node * D + lane * 4) = r;
}

// ---------------------------------------------------------------------------
// Launch — kernel launches + captured event fork/join (graph-capture safe;
// stream/events created on the FIRST call, which the harness runs uncaptured)
// ---------------------------------------------------------------------------
extern "C" void kernel_launch(void* const* d_in, const int* in_sizes, int n_in,
                              void* d_out, int out_size) {
    const float* x  = (const float*)d_in[0];
    const int*   ei = (const int*)d_in[1];
    const float* W1 = (const float*)d_in[2];
    const float* b1 = (const float*)d_in[3];
    const float* W2 = (const float*)d_in[4];
    const float* b2 = (const float*)d_in[5];
    float* out = (float*)d_out;

    static cudaStream_t s2 = nullptr;
    static cudaEvent_t evFork = nullptr, evJoin = nullptr;
    if (!s2) {
        cudaFuncSetAttribute(gemm1_kernel,
                             cudaFuncAttributeMaxDynamicSharedMemorySize,
                             GEMM_DSMEM);
        cudaFuncSetAttribute(gemm2_kernel,
                             cudaFuncAttributeMaxDynamicSharedMemorySize,
                             GEMM_DSMEM);
        cudaStreamCreateWithFlags(&s2, cudaStreamNonBlocking);
        cudaEventCreateWithFlags(&evFork, cudaEventDisableTiming);
        cudaEventCreateWithFlags(&evJoin, cudaEventDisableTiming);
    }

    const int T = 256;
    const int nb_n    = (NN + T - 1) / T;
    const int nb_e    = (EE + T - 1) / T;
    const int nb_gath = (NN * 32 + T - 1) / T;

    // Main stream: detect width + degree histogram (cnt enters zeroed:
    // BSS-init on first call, re-zeroed by gather1 on every run)
    detect_kernel<<<1, 32>>>(ei);
    hist_kernel<<<nb_e, T>>>(ei);

    // Fork: side branch computes prepw + dinv + gemm1 (needs only cnt),
    // while main does scan + fill (CSR build). Disjoint write sets.
    cudaEventRecord(evFork, 0);
    cudaStreamWaitEvent(s2, evFork, 0);

    prepw_kernel<<<64, 256, 0, s2>>>(W1, W2);
    dinv_kernel<<<nb_n, T, 0, s2>>>();
    gemm1_kernel<<<NTILES, 512, GEMM_DSMEM, s2>>>(x);
    cudaEventRecord(evJoin, s2);

    // Main: CSR build (scan2 merged into scan3)
    scan1_kernel<<<SCAN_NBLK, SCAN_CHUNK>>>();
    scan3_kernel<<<nb_n, T>>>();
    fill_kernel<<<nb_e, T>>>(ei);

    // Join: gather1 needs CSR + g_h16 + dinv
    cudaStreamWaitEvent(0, evJoin, 0);

    gather1_kernel<<<nb_gath, T>>>(b1);
    gemm2_kernel<<<NTILES, 512, GEMM_DSMEM>>>();
    gather2_kernel<<<nb_gath, T>>>(b2, out);
}